// round 1
// baseline (speedup 1.0000x reference)
#include <cuda_runtime.h>

// Zonotope propagation: D=1024 -> H=4096 -> H=4096 -> O=10
// Key insight: initial eps is diagonal => layer-1 "GEMM" is column scaling;
// only W2 @ E1' (4096x4096 @ 4096x1026) is a real GEMM.

#define DD 1024
#define HH 4096
#define OO 10
#define SB 1152          // padded column stride (9 * 128) for Baug / E2
#define NC3 1027         // layer-3 B columns: 1025 eps + t2 + v2'
#define SE3 1056         // padded stride for E3 partials
#define KS3 16           // deterministic k-split for layer-3 GEMM

#define C_EPS   0.01f
#define C_MEAN  0.1307f
#define C_SIGMA 0.3081f

// ---- device scratch (no allocations allowed) ----
__device__ float g_v0[DD];
__device__ float g_d[DD];
__device__ float g_s1[HH];
__device__ float g_t1[HH];
__device__ float g_v1p[HH];
__device__ float g_Baug[HH * SB];   // 18.9 MB
__device__ float g_E2[HH * SB];     // 18.9 MB
__device__ float g_s2[HH];
__device__ float g_t2[HH];
__device__ float g_v2p[HH];
__device__ float g_E3p[KS3 * OO * SE3];

static __device__ __forceinline__ void relu_params(float v, float r,
                                                   float& s, float& t, float& vn) {
    float u = v + r;
    float l = v - r;
    if (u <= 0.f) {                 // dead
        s = 0.f; t = 0.f; vn = 0.f;
    } else if (l < 0.f) {           // crossing (denom = u-l = 2r > 0 here)
        float slope = u / (u - l);
        float term  = (1.f - slope) * u * 0.5f;
        s = slope; t = term; vn = slope * v + term;
    } else {                        // stable active
        s = 1.f; t = 0.f; vn = v;
    }
}

// ---- K0: initial zonotope build + normalize ----
__global__ void k0_init(const float* __restrict__ in) {
    int j = threadIdx.x;            // one block of 1024
    float x  = in[j];
    float up = fminf(x + C_EPS, 1.f);
    float lo = fmaxf(x - C_EPS, 0.f);
    float val = up + lo;            // faithful to source: values = u + l
    g_v0[j] = (val - C_MEAN) / C_SIGMA;
    g_d[j]  = up / C_SIGMA;         // (values - lower) = upper, then /SIGMA, >= 0
}

// ---- K1: layer-1 matvec + radius + ReLU-zono params (warp per row) ----
__global__ void k1_layer1(const float* __restrict__ W1, const float* __restrict__ b1) {
    int row  = blockIdx.x * 8 + (threadIdx.x >> 5);
    int lane = threadIdx.x & 31;
    const float* w = W1 + (size_t)row * DD;
    float sv = 0.f, sr = 0.f;
    #pragma unroll
    for (int j = lane * 4; j < DD; j += 128) {
        float4 wv = *(const float4*)(w + j);
        float4 v  = *(const float4*)(g_v0 + j);
        float4 dd = *(const float4*)(g_d + j);
        sv += wv.x * v.x + wv.y * v.y + wv.z * v.z + wv.w * v.w;
        sr += fabsf(wv.x) * dd.x + fabsf(wv.y) * dd.y
            + fabsf(wv.z) * dd.z + fabsf(wv.w) * dd.w;   // d >= 0
    }
    #pragma unroll
    for (int o = 16; o; o >>= 1) {
        sv += __shfl_xor_sync(0xffffffffu, sv, o);
        sr += __shfl_xor_sync(0xffffffffu, sr, o);
    }
    if (lane == 0) {
        float v = sv + b1[row];
        float s, t, vn;
        relu_params(v, sr, s, t, vn);
        g_s1[row] = s; g_t1[row] = t; g_v1p[row] = vn;
    }
}

// ---- K2: materialize augmented B for the big GEMM ----
// col j<1024: s1[k]*W1[k][j]*d[j];  col 1024: t1[k];  col 1025: v1p[k];  else 0
__global__ void k2_build(const float* __restrict__ W1) {
    int idx = blockIdx.x * blockDim.x + threadIdx.x;   // float4 index
    int k  = idx / (SB / 4);
    int j4 = (idx - k * (SB / 4)) * 4;
    float4 out;
    if (j4 < DD) {   // DD divisible by 4 -> whole float4 in range
        float s = g_s1[k];
        float4 w  = *(const float4*)(W1 + (size_t)k * DD + j4);
        float4 dd = *(const float4*)(g_d + j4);
        out.x = s * w.x * dd.x; out.y = s * w.y * dd.y;
        out.z = s * w.z * dd.z; out.w = s * w.w * dd.w;
    } else {
        float v[4];
        #pragma unroll
        for (int q = 0; q < 4; q++) {
            int j = j4 + q;
            v[q] = (j == DD) ? g_t1[k] : (j == DD + 1 ? g_v1p[k] : 0.f);
        }
        out.x = v[0]; out.y = v[1]; out.z = v[2]; out.w = v[3];
    }
    *(float4*)(g_Baug + (size_t)k * SB + j4) = out;
}

// ---- K3: E2 = W2 @ Baug  (4096 x 1152 x 4096 fp32 SGEMM) ----
// 128x128 block tile, 8x8/thread, BK=16, double-buffered smem.
#define BM 128
#define BN 128
#define BK 16

__global__ __launch_bounds__(256) void k3_gemm(const float* __restrict__ A) {
    __shared__ float As[2][BM][BK + 1];   // [m][k], padded stride 17
    __shared__ float Bs[2][BK][BN];

    const int tid = threadIdx.x;
    const int i0 = blockIdx.y * BM;
    const int j0 = blockIdx.x * BN;
    const int ty = tid >> 4;          // 0..15 -> row group
    const int tx = tid & 15;          // 0..15 -> col group

    const int a_r = tid >> 2;         // 0..63
    const int a_k = (tid & 3) * 4;    // 0,4,8,12
    const int b_k = tid >> 5;         // 0..7
    const int b_n = (tid & 31) * 4;   // 0..124

    const float* Ap0 = A + (size_t)(i0 + a_r) * HH + a_k;
    const float* Ap1 = A + (size_t)(i0 + a_r + 64) * HH + a_k;
    const float* Bp0 = g_Baug + (size_t)b_k * SB + j0 + b_n;
    const float* Bp1 = g_Baug + (size_t)(b_k + 8) * SB + j0 + b_n;

    float4 ar0 = *(const float4*)(Ap0);
    float4 ar1 = *(const float4*)(Ap1);
    float4 br0 = *(const float4*)(Bp0);
    float4 br1 = *(const float4*)(Bp1);

    // store tile 0 into buffer 0
    As[0][a_r     ][a_k + 0] = ar0.x; As[0][a_r     ][a_k + 1] = ar0.y;
    As[0][a_r     ][a_k + 2] = ar0.z; As[0][a_r     ][a_k + 3] = ar0.w;
    As[0][a_r + 64][a_k + 0] = ar1.x; As[0][a_r + 64][a_k + 1] = ar1.y;
    As[0][a_r + 64][a_k + 2] = ar1.z; As[0][a_r + 64][a_k + 3] = ar1.w;
    *(float4*)&Bs[0][b_k    ][b_n] = br0;
    *(float4*)&Bs[0][b_k + 8][b_n] = br1;
    __syncthreads();

    float acc[8][8];
    #pragma unroll
    for (int m = 0; m < 8; m++)
        #pragma unroll
        for (int n = 0; n < 8; n++) acc[m][n] = 0.f;

    const int nk = HH / BK;   // 256
    for (int t = 0; t < nk; ++t) {
        const int buf = t & 1;
        if (t + 1 < nk) {
            size_t ko = (size_t)(t + 1) * BK;
            ar0 = *(const float4*)(Ap0 + ko);
            ar1 = *(const float4*)(Ap1 + ko);
            br0 = *(const float4*)(Bp0 + ko * SB);
            br1 = *(const float4*)(Bp1 + ko * SB);
        }
        #pragma unroll
        for (int kk = 0; kk < BK; ++kk) {
            float a[8], b[8];
            #pragma unroll
            for (int m = 0; m < 8; m++) a[m] = As[buf][ty * 8 + m][kk];  // broadcast
            *(float4*)&b[0] = *(const float4*)&Bs[buf][kk][tx * 8];
            *(float4*)&b[4] = *(const float4*)&Bs[buf][kk][tx * 8 + 4];
            #pragma unroll
            for (int m = 0; m < 8; m++)
                #pragma unroll
                for (int n = 0; n < 8; n++)
                    acc[m][n] += a[m] * b[n];
        }
        if (t + 1 < nk) {
            const int nb = buf ^ 1;
            As[nb][a_r     ][a_k + 0] = ar0.x; As[nb][a_r     ][a_k + 1] = ar0.y;
            As[nb][a_r     ][a_k + 2] = ar0.z; As[nb][a_r     ][a_k + 3] = ar0.w;
            As[nb][a_r + 64][a_k + 0] = ar1.x; As[nb][a_r + 64][a_k + 1] = ar1.y;
            As[nb][a_r + 64][a_k + 2] = ar1.z; As[nb][a_r + 64][a_k + 3] = ar1.w;
            *(float4*)&Bs[nb][b_k    ][b_n] = br0;
            *(float4*)&Bs[nb][b_k + 8][b_n] = br1;
        }
        __syncthreads();
    }

    #pragma unroll
    for (int m = 0; m < 8; m++) {
        size_t ro = (size_t)(i0 + ty * 8 + m) * SB + j0 + tx * 8;
        float4 c0 = make_float4(acc[m][0], acc[m][1], acc[m][2], acc[m][3]);
        float4 c1 = make_float4(acc[m][4], acc[m][5], acc[m][6], acc[m][7]);
        *(float4*)(g_E2 + ro)     = c0;
        *(float4*)(g_E2 + ro + 4) = c1;
    }
}

// ---- K4: row-wise |.| reduce over E2 + ReLU-zono params (warp per row) ----
__global__ void k4_relu2(const float* __restrict__ b2) {
    int row  = blockIdx.x * 8 + (threadIdx.x >> 5);
    int lane = threadIdx.x & 31;
    const float* e = g_E2 + (size_t)row * SB;
    float sr = 0.f;
    #pragma unroll 4
    for (int j = lane * 4; j < DD; j += 128) {
        float4 x = *(const float4*)(e + j);
        sr += fabsf(x.x) + fabsf(x.y) + fabsf(x.z) + fabsf(x.w);
    }
    #pragma unroll
    for (int o = 16; o; o >>= 1) sr += __shfl_xor_sync(0xffffffffu, sr, o);
    if (lane == 0) {
        sr += fabsf(e[DD]);                 // t1-derived column (index 1024)
        float v = e[DD + 1] + b2[row];      // value column (index 1025)
        float s, t, vn;
        relu_params(v, sr, s, t, vn);
        g_s2[row] = s; g_t2[row] = t; g_v2p[row] = vn;
    }
}

// ---- K5: layer-3 partial GEMM, deterministic 16-way k-split ----
// B col j<1025: s2[k]*E2[k][j];  j==1025: t2[k];  j==1026: v2p[k]
__global__ void k5_e3(const float* __restrict__ W3) {
    __shared__ float w3s[OO][256];
    __shared__ float s2s[256];
    const int jt = blockIdx.x, ks = blockIdx.y;
    const int k0 = ks * 256;
    const int tid = threadIdx.x;   // 128 threads

    for (int idx = tid; idx < OO * 256; idx += 128) {
        int i = idx >> 8, kk = idx & 255;
        w3s[i][kk] = W3[(size_t)i * HH + k0 + kk];
    }
    for (int kk = tid; kk < 256; kk += 128) s2s[kk] = g_s2[k0 + kk];
    __syncthreads();

    const int j = jt * 128 + tid;
    float acc[OO];
    #pragma unroll
    for (int i = 0; i < OO; i++) acc[i] = 0.f;

    if (j < 1025) {
        const float* e = g_E2 + (size_t)k0 * SB + j;
        for (int kk = 0; kk < 256; ++kk) {
            float bval = s2s[kk] * e[(size_t)kk * SB];
            #pragma unroll
            for (int i = 0; i < OO; i++) acc[i] += w3s[i][kk] * bval;
        }
    } else if (j == 1025) {
        for (int kk = 0; kk < 256; ++kk) {
            float bval = g_t2[k0 + kk];
            #pragma unroll
            for (int i = 0; i < OO; i++) acc[i] += w3s[i][kk] * bval;
        }
    } else if (j == 1026) {
        for (int kk = 0; kk < 256; ++kk) {
            float bval = g_v2p[k0 + kk];
            #pragma unroll
            for (int i = 0; i < OO; i++) acc[i] += w3s[i][kk] * bval;
        }
    }
    if (j < NC3) {
        #pragma unroll
        for (int i = 0; i < OO; i++)
            g_E3p[((size_t)ks * OO + i) * SE3 + j] = acc[i];
    }
}

// ---- K6: reduce k-splits, final bounds. out[0..9]=u, out[10..19]=l ----
__global__ void k6_final(const float* __restrict__ b3, float* __restrict__ out) {
    const int i = blockIdx.x;
    const int tid = threadIdx.x;   // 256
    __shared__ float red[256];
    __shared__ float vsh;
    float racc = 0.f;
    for (int j = tid; j < NC3; j += 256) {
        float s = 0.f;
        #pragma unroll
        for (int ks = 0; ks < KS3; ks++) s += g_E3p[((size_t)ks * OO + i) * SE3 + j];
        if (j < 1026) racc += fabsf(s);
        else          vsh = s + b3[i];     // j == 1026: value column
    }
    red[tid] = racc;
    __syncthreads();
    for (int o = 128; o; o >>= 1) {
        if (tid < o) red[tid] += red[tid + o];
        __syncthreads();
    }
    if (tid == 0) {
        float v = vsh, r = red[0];
        out[i]      = v + r;   // upper
        out[10 + i] = v - r;   // lower
    }
}

extern "C" void kernel_launch(void* const* d_in, const int* in_sizes, int n_in,
                              void* d_out, int out_size) {
    const float* inputs = (const float*)d_in[0];
    const float* W1     = (const float*)d_in[1];
    const float* b1     = (const float*)d_in[2];
    const float* W2     = (const float*)d_in[3];
    const float* b2     = (const float*)d_in[4];
    const float* W3     = (const float*)d_in[5];
    const float* b3     = (const float*)d_in[6];
    float* out = (float*)d_out;

    k0_init<<<1, DD>>>(inputs);
    k1_layer1<<<HH / 8, 256>>>(W1, b1);
    k2_build<<<(HH * (SB / 4)) / 256, 256>>>(W1);
    dim3 g3(SB / BN, HH / BM);          // 9 x 32 = 288 blocks
    k3_gemm<<<g3, 256>>>(W2);
    k4_relu2<<<HH / 8, 256>>>(b2);
    dim3 g5(9, KS3);
    k5_e3<<<g5, 128>>>(W3);
    k6_final<<<OO, 256>>>(b3, out);
}

// round 3
// speedup vs baseline: 2.4615x; 2.4615x over previous
#include <cuda_runtime.h>
#include <cuda_bf16.h>
#include <cstdint>

// Zonotope propagation: D=1024 -> H=4096 -> H=4096 -> O=10
// Heavy op: E2 = W2 @ Baug (4096x4096 @ 4096x1152), via mma.sync bf16 with a
// 3-way hi/lo split: AhBh + AhBl + AlBh (fp32 accumulate) -> ~1e-6 accuracy.

#define DD 1024
#define HH 4096
#define OO 10
#define SB 1152          // padded column count for E2 (9*128)
#define NC3 1027
#define SE3 1056
#define KS3 16

#define C_EPS   0.01f
#define C_MEAN  0.1307f
#define C_SIGMA 0.3081f

// ---- device scratch ----
__device__ float g_v0[DD];
__device__ float g_d[DD];
__device__ float g_s1[HH];
__device__ float g_t1[HH];
__device__ float g_v1p[HH];
__device__ __nv_bfloat16 g_W2h[(size_t)HH * HH];   // 33.5 MB
__device__ __nv_bfloat16 g_W2l[(size_t)HH * HH];   // 33.5 MB
__device__ __nv_bfloat16 g_BTh[(size_t)SB * HH];   // 9.4 MB  (BaugT, K-major)
__device__ __nv_bfloat16 g_BTl[(size_t)SB * HH];   // 9.4 MB
__device__ float g_E2[(size_t)HH * SB];            // 18.9 MB
__device__ float g_s2[HH];
__device__ float g_t2[HH];
__device__ float g_v2p[HH];
__device__ float g_E3p[KS3 * OO * SE3];

// ================= PTX helpers (base-PTX only, no sm_103a-gated ops) ==========
static __device__ __forceinline__ uint32_t smem_u32(const void* p) {
    uint32_t a;
    asm("{ .reg .u64 t; cvta.to.shared.u64 t, %1; cvt.u32.u64 %0, t; }" : "=r"(a) : "l"(p));
    return a;
}
static __device__ __forceinline__ void cp16(uint32_t dst, const void* src) {
    asm volatile("cp.async.cg.shared.global [%0], [%1], 16;" :: "r"(dst), "l"(src));
}
static __device__ __forceinline__ void cp_commit() {
    asm volatile("cp.async.commit_group;" ::: "memory");
}
template <int N> static __device__ __forceinline__ void cp_wait() {
    asm volatile("cp.async.wait_group %0;" :: "n"(N) : "memory");
}
#define LDSM4(r0, r1, r2, r3, addr) \
    asm volatile("ldmatrix.sync.aligned.m8n8.x4.shared.b16 {%0,%1,%2,%3}, [%4];" \
                 : "=r"(r0), "=r"(r1), "=r"(r2), "=r"(r3) : "r"(addr))
#define MMA16816(c, a, b) \
    asm volatile("mma.sync.aligned.m16n8k16.row.col.f32.bf16.bf16.f32 " \
                 "{%0,%1,%2,%3}, {%4,%5,%6,%7}, {%8,%9}, {%0,%1,%2,%3};" \
                 : "+f"((c)[0]), "+f"((c)[1]), "+f"((c)[2]), "+f"((c)[3]) \
                 : "r"((a)[0]), "r"((a)[1]), "r"((a)[2]), "r"((a)[3]), \
                   "r"((b)[0]), "r"((b)[1]))

static __device__ __forceinline__ void relu_params(float v, float r,
                                                   float& s, float& t, float& vn) {
    float u = v + r;
    float l = v - r;
    if (u <= 0.f)       { s = 0.f; t = 0.f; vn = 0.f; }
    else if (l < 0.f)   { float slope = u / (u - l); float term = (1.f - slope) * u * 0.5f;
                          s = slope; t = term; vn = slope * v + term; }
    else                { s = 1.f; t = 0.f; vn = v; }
}
static __device__ __forceinline__ void split_hl(float x, __nv_bfloat16& h, __nv_bfloat16& l) {
    h = __float2bfloat16_rn(x);
    l = __float2bfloat16_rn(x - __bfloat162float(h));
}

// ---- K0: initial zonotope ----
__global__ void k0_init(const float* __restrict__ in) {
    int j = threadIdx.x;
    float x  = in[j];
    float up = fminf(x + C_EPS, 1.f);
    float lo = fmaxf(x - C_EPS, 0.f);
    float val = up + lo;
    g_v0[j] = (val - C_MEAN) / C_SIGMA;
    g_d[j]  = up / C_SIGMA;
}

// ---- K1: layer-1 matvec + radius + ReLU params ----
__global__ void k1_layer1(const float* __restrict__ W1, const float* __restrict__ b1) {
    int row  = blockIdx.x * 8 + (threadIdx.x >> 5);
    int lane = threadIdx.x & 31;
    const float* w = W1 + (size_t)row * DD;
    float sv = 0.f, sr = 0.f;
    #pragma unroll
    for (int j = lane * 4; j < DD; j += 128) {
        float4 wv = *(const float4*)(w + j);
        float4 v  = *(const float4*)(g_v0 + j);
        float4 dd = *(const float4*)(g_d + j);
        sv += wv.x * v.x + wv.y * v.y + wv.z * v.z + wv.w * v.w;
        sr += fabsf(wv.x) * dd.x + fabsf(wv.y) * dd.y
            + fabsf(wv.z) * dd.z + fabsf(wv.w) * dd.w;
    }
    #pragma unroll
    for (int o = 16; o; o >>= 1) {
        sv += __shfl_xor_sync(0xffffffffu, sv, o);
        sr += __shfl_xor_sync(0xffffffffu, sr, o);
    }
    if (lane == 0) {
        float v = sv + b1[row];
        float s, t, vn;
        relu_params(v, sr, s, t, vn);
        g_s1[row] = s; g_t1[row] = t; g_v1p[row] = vn;
    }
}

// ---- K2a: split W2 into bf16 hi/lo ----
__global__ void k2a_convW2(const float* __restrict__ W2) {
    size_t i4 = (size_t)blockIdx.x * blockDim.x + threadIdx.x;
    float4 x = *(const float4*)(W2 + i4 * 4);
    __nv_bfloat16 h0,h1,h2,h3,l0,l1,l2,l3;
    split_hl(x.x,h0,l0); split_hl(x.y,h1,l1); split_hl(x.z,h2,l2); split_hl(x.w,h3,l3);
    ushort4 hh = make_ushort4(__bfloat16_as_ushort(h0), __bfloat16_as_ushort(h1),
                              __bfloat16_as_ushort(h2), __bfloat16_as_ushort(h3));
    ushort4 ll = make_ushort4(__bfloat16_as_ushort(l0), __bfloat16_as_ushort(l1),
                              __bfloat16_as_ushort(l2), __bfloat16_as_ushort(l3));
    *(ushort4*)((unsigned short*)g_W2h + i4 * 4) = hh;
    *(ushort4*)((unsigned short*)g_W2l + i4 * 4) = ll;
}

// ---- K2b: build BaugT rows 0..1023 (scaled W1 transpose), bf16 hi/lo ----
// BaugT[j][k] = s1[k] * W1[k][j] * d[j]
__global__ void k2b_buildBT(const float* __restrict__ W1) {
    __shared__ float ts[32][33];
    int k0 = blockIdx.x * 32;
    int j0 = blockIdx.y * 32;
    int tx = threadIdx.x & 31, ty = threadIdx.x >> 5;   // 32 x 8
    #pragma unroll
    for (int r = 0; r < 4; r++) {
        int k = k0 + ty + r * 8;
        ts[ty + r * 8][tx] = W1[(size_t)k * DD + j0 + tx] * g_s1[k];
    }
    __syncthreads();
    #pragma unroll
    for (int r = 0; r < 4; r++) {
        int j = j0 + ty + r * 8;
        float x = ts[tx][ty + r * 8] * g_d[j];
        __nv_bfloat16 h, l; split_hl(x, h, l);
        g_BTh[(size_t)j * HH + k0 + tx] = h;
        g_BTl[(size_t)j * HH + k0 + tx] = l;
    }
}

// ---- K2c: BaugT rows 1024..1151 (t1 row, v1p row, zero pad) ----
__global__ void k2c_tailBT() {
    int idx = blockIdx.x * blockDim.x + threadIdx.x;
    int rl = idx >> 12;            // 0..127
    int k  = idx & 4095;
    float x = (rl == 0) ? g_t1[k] : (rl == 1 ? g_v1p[k] : 0.f);
    __nv_bfloat16 h, l; split_hl(x, h, l);
    g_BTh[(size_t)(DD + rl) * HH + k] = h;
    g_BTl[(size_t)(DD + rl) * HH + k] = l;
}

// ================== K3: mma.sync bf16 GEMM ==================
// E2[i][j] = sum_k A[i][k] * BaugT[j][k].  CTA tile 128(M) x 128(N), BK=32.
// 8 warps in 4(M) x 2(N); warp tile 32x64 via m16n8k16.
// Smem chunk swizzle: 16B chunk p = c ^ ((row>>1)&3)  (conflict-free STS + LDSM).
#define KITERS 384    // 3 phases x 128

__global__ __launch_bounds__(256) void k3_mma() {
    __shared__ __align__(1024) unsigned char sm[2 * 16384];   // 2 stages x (A 8K + B 8K)
    const int tid  = threadIdx.x;
    const int lane = tid & 31;
    const int wid  = tid >> 5;
    const int warp_m = wid & 3;        // 0..3 -> M offset 32*warp_m
    const int warp_n = wid >> 2;       // 0..1 -> N offset 64*warp_n
    const int i0 = blockIdx.y * 128;
    const int j0 = blockIdx.x * 128;
    const uint32_t sbase = smem_u32(sm);

    // ldmatrix source offsets (within a stage); A rows: 16-row frag, B rows: n
    const int ra = (lane & 7) + (((lane >> 3) & 1) << 3);   // row-in-16 for A
    const int ha = lane >> 4;                               // k-half for A
    const int rb = (lane & 7) + ((lane >> 4) << 3);         // row-in-16 for B
    const int hb = (lane >> 3) & 1;                         // k-half for B
    uint32_t offA[2][2], offB[4][2];
    #pragma unroll
    for (int mf = 0; mf < 2; mf++)
        #pragma unroll
        for (int kk = 0; kk < 2; kk++) {
            int row = warp_m * 32 + mf * 16 + ra;
            int c   = kk * 2 + ha;
            offA[mf][kk] = row * 64 + ((c ^ ((row >> 1) & 3)) << 4);
        }
    #pragma unroll
    for (int nf4 = 0; nf4 < 4; nf4++)
        #pragma unroll
        for (int kk = 0; kk < 2; kk++) {
            int row = warp_n * 64 + nf4 * 16 + rb;
            int c   = kk * 2 + hb;
            offB[nf4][kk] = 8192 + row * 64 + ((c ^ ((row >> 1) & 3)) << 4);
        }

    // cp.async fill: 1024 16B chunks (A 512 + B 512), 4 per thread
    const int f_row = (tid >> 2) & 127;         // reused for A and B halves
    const int f_c   = tid & 3;
    const uint32_t f_swoff = f_row * 64 + ((f_c ^ ((f_row >> 1) & 3)) << 4);

    auto fill = [&](int stage, int t) {
        const __nv_bfloat16* Wp = (t < 256) ? g_W2h : g_W2l;
        const __nv_bfloat16* Bp = (t < 128 || t >= 256) ? g_BTh : g_BTl;
        const int kg = (t & 127) * 32;
        const uint32_t base = sbase + stage * 16384;
        // A: rows f_row, f_row+64 ; B: same
        cp16(base + f_swoff,                     Wp + (size_t)(i0 + f_row) * HH + kg + f_c * 8);
        {
            int r2 = f_row ^ 64;   // covers other 64 rows (f_row in 0..127 from tid>>2? tid>>2 max 63)
            (void)r2;
        }
        // tid>>2 spans 0..63 only; do 2 A rows + 2 B rows explicitly:
        {
            int rA0 = (tid >> 2);            // 0..63
            int rA1 = rA0 + 64;
            uint32_t swA0 = rA0 * 64 + ((f_c ^ ((rA0 >> 1) & 3)) << 4);
            uint32_t swA1 = rA1 * 64 + ((f_c ^ ((rA1 >> 1) & 3)) << 4);
            cp16(base + swA0, Wp + (size_t)(i0 + rA0) * HH + kg + f_c * 8);
            cp16(base + swA1, Wp + (size_t)(i0 + rA1) * HH + kg + f_c * 8);
            cp16(base + 8192 + swA0, Bp + (size_t)(j0 + rA0) * HH + kg + f_c * 8);
            cp16(base + 8192 + swA1, Bp + (size_t)(j0 + rA1) * HH + kg + f_c * 8);
        }
        cp_commit();
    };

    float acc[2][8][4];
    #pragma unroll
    for (int mf = 0; mf < 2; mf++)
        #pragma unroll
        for (int nf = 0; nf < 8; nf++)
            #pragma unroll
            for (int q = 0; q < 4; q++) acc[mf][nf][q] = 0.f;

    fill(0, 0);
    for (int t = 0; t < KITERS; ++t) {
        const int buf = t & 1;
        if (t + 1 < KITERS) { fill(buf ^ 1, t + 1); cp_wait<1>(); }
        else                { cp_wait<0>(); }
        __syncthreads();
        const uint32_t base = sbase + buf * 16384;
        #pragma unroll
        for (int kk = 0; kk < 2; kk++) {
            uint32_t a[2][4], b[8][2];
            #pragma unroll
            for (int mf = 0; mf < 2; mf++)
                LDSM4(a[mf][0], a[mf][1], a[mf][2], a[mf][3], base + offA[mf][kk]);
            #pragma unroll
            for (int nf4 = 0; nf4 < 4; nf4++) {
                uint32_t r0, r1, r2, r3;
                LDSM4(r0, r1, r2, r3, base + offB[nf4][kk]);
                b[nf4 * 2][0] = r0; b[nf4 * 2][1] = r1;
                b[nf4 * 2 + 1][0] = r2; b[nf4 * 2 + 1][1] = r3;
            }
            #pragma unroll
            for (int mf = 0; mf < 2; mf++)
                #pragma unroll
                for (int nf = 0; nf < 8; nf++)
                    MMA16816(acc[mf][nf], a[mf], b[nf]);
        }
        __syncthreads();
    }

    // epilogue: C fragment -> g_E2
    const int er = lane >> 2;
    const int ec = (lane & 3) * 2;
    #pragma unroll
    for (int mf = 0; mf < 2; mf++) {
        #pragma unroll
        for (int nf = 0; nf < 8; nf++) {
            int row = i0 + warp_m * 32 + mf * 16 + er;
            int col = j0 + warp_n * 64 + nf * 8 + ec;
            *(float2*)(g_E2 + (size_t)row * SB + col)       = make_float2(acc[mf][nf][0], acc[mf][nf][1]);
            *(float2*)(g_E2 + (size_t)(row + 8) * SB + col) = make_float2(acc[mf][nf][2], acc[mf][nf][3]);
        }
    }
}

// ---- K4: row-wise |.| reduce over E2 + ReLU params ----
__global__ void k4_relu2(const float* __restrict__ b2) {
    int row  = blockIdx.x * 8 + (threadIdx.x >> 5);
    int lane = threadIdx.x & 31;
    const float* e = g_E2 + (size_t)row * SB;
    float sr = 0.f;
    #pragma unroll 4
    for (int j = lane * 4; j < DD; j += 128) {
        float4 x = *(const float4*)(e + j);
        sr += fabsf(x.x) + fabsf(x.y) + fabsf(x.z) + fabsf(x.w);
    }
    #pragma unroll
    for (int o = 16; o; o >>= 1) sr += __shfl_xor_sync(0xffffffffu, sr, o);
    if (lane == 0) {
        sr += fabsf(e[DD]);
        float v = e[DD + 1] + b2[row];
        float s, t, vn;
        relu_params(v, sr, s, t, vn);
        g_s2[row] = s; g_t2[row] = t; g_v2p[row] = vn;
    }
}

// ---- K5: layer-3 partial GEMM (16-way deterministic k-split) ----
__global__ void k5_e3(const float* __restrict__ W3) {
    __shared__ float w3s[OO][256];
    __shared__ float s2s[256];
    const int jt = blockIdx.x, ks = blockIdx.y;
    const int k0 = ks * 256;
    const int tid = threadIdx.x;

    for (int idx = tid; idx < OO * 256; idx += 128) {
        int i = idx >> 8, kk = idx & 255;
        w3s[i][kk] = W3[(size_t)i * HH + k0 + kk];
    }
    for (int kk = tid; kk < 256; kk += 128) s2s[kk] = g_s2[k0 + kk];
    __syncthreads();

    const int j = jt * 128 + tid;
    float acc[OO];
    #pragma unroll
    for (int i = 0; i < OO; i++) acc[i] = 0.f;

    if (j < 1025) {
        const float* e = g_E2 + (size_t)k0 * SB + j;
        for (int kk = 0; kk < 256; ++kk) {
            float bval = s2s[kk] * e[(size_t)kk * SB];
            #pragma unroll
            for (int i = 0; i < OO; i++) acc[i] += w3s[i][kk] * bval;
        }
    } else if (j == 1025) {
        for (int kk = 0; kk < 256; ++kk) {
            float bval = g_t2[k0 + kk];
            #pragma unroll
            for (int i = 0; i < OO; i++) acc[i] += w3s[i][kk] * bval;
        }
    } else if (j == 1026) {
        for (int kk = 0; kk < 256; ++kk) {
            float bval = g_v2p[k0 + kk];
            #pragma unroll
            for (int i = 0; i < OO; i++) acc[i] += w3s[i][kk] * bval;
        }
    }
    if (j < NC3) {
        #pragma unroll
        for (int i = 0; i < OO; i++)
            g_E3p[((size_t)ks * OO + i) * SE3 + j] = acc[i];
    }
}

// ---- K6: reduce splits + final bounds ----
__global__ void k6_final(const float* __restrict__ b3, float* __restrict__ out) {
    const int i = blockIdx.x;
    const int tid = threadIdx.x;
    __shared__ float red[256];
    __shared__ float vsh;
    float racc = 0.f;
    for (int j = tid; j < NC3; j += 256) {
        float s = 0.f;
        #pragma unroll
        for (int ks = 0; ks < KS3; ks++) s += g_E3p[((size_t)ks * OO + i) * SE3 + j];
        if (j < 1026) racc += fabsf(s);
        else          vsh = s + b3[i];
    }
    red[tid] = racc;
    __syncthreads();
    for (int o = 128; o; o >>= 1) {
        if (tid < o) red[tid] += red[tid + o];
        __syncthreads();
    }
    if (tid == 0) {
        float v = vsh, r = red[0];
        out[i]      = v + r;
        out[10 + i] = v - r;
    }
}

extern "C" void kernel_launch(void* const* d_in, const int* in_sizes, int n_in,
                              void* d_out, int out_size) {
    const float* inputs = (const float*)d_in[0];
    const float* W1     = (const float*)d_in[1];
    const float* b1     = (const float*)d_in[2];
    const float* W2     = (const float*)d_in[3];
    const float* b2     = (const float*)d_in[4];
    const float* W3     = (const float*)d_in[5];
    const float* b3     = (const float*)d_in[6];
    float* out = (float*)d_out;

    k0_init<<<1, DD>>>(inputs);
    k1_layer1<<<HH / 8, 256>>>(W1, b1);
    k2a_convW2<<<((size_t)HH * HH / 4) / 256, 256>>>(W2);
    dim3 g2b(HH / 32, DD / 32);
    k2b_buildBT<<<g2b, 256>>>(W1);
    k2c_tailBT<<<(128 * HH) / 256, 256>>>();
    dim3 g3(SB / 128, HH / 128);           // 9 x 32 = 288 CTAs
    k3_mma<<<g3, 256>>>();
    k4_relu2<<<HH / 8, 256>>>(b2);
    dim3 g5(9, KS3);
    k5_e3<<<g5, 128>>>(W3);
    k6_final<<<OO, 256>>>(b3, out);
}

// round 4
// speedup vs baseline: 2.9789x; 1.2102x over previous
#include <cuda_runtime.h>
#include <cuda_bf16.h>
#include <cstdint>

// Zonotope propagation: D=1024 -> H=4096 -> H=4096 -> O=10
// Heavy op: E2 = W2 @ Baug (4096x4096 @ 4096x1152), via mma.sync bf16 with a
// 3-way hi/lo split: AhBh + AhBl + AlBh (fp32 accumulate) -> ~2e-5 accuracy.
// R4: 256x128 CTA tile (144 CTAs = 1 wave), merged 3-pass stages {Ah,Al,Bh,Bl},
//     3-stage cp.async ring, 1 syncthreads per k-group.

#define DD 1024
#define HH 4096
#define OO 10
#define SB 1152
#define NC3 1027
#define SE3 1056
#define KS3 16

#define C_EPS   0.01f
#define C_MEAN  0.1307f
#define C_SIGMA 0.3081f

// ---- device scratch ----
__device__ float g_v0[DD];
__device__ float g_d[DD];
__device__ float g_s1[HH];
__device__ float g_t1[HH];
__device__ float g_v1p[HH];
__device__ __nv_bfloat16 g_W2h[(size_t)HH * HH];
__device__ __nv_bfloat16 g_W2l[(size_t)HH * HH];
__device__ __nv_bfloat16 g_BTh[(size_t)SB * HH];
__device__ __nv_bfloat16 g_BTl[(size_t)SB * HH];
__device__ float g_E2[(size_t)HH * SB];
__device__ float g_s2[HH];
__device__ float g_t2[HH];
__device__ float g_v2p[HH];
__device__ float g_E3p[KS3 * OO * SE3];

// ================= PTX helpers =================
static __device__ __forceinline__ uint32_t smem_u32(const void* p) {
    uint32_t a;
    asm("{ .reg .u64 t; cvta.to.shared.u64 t, %1; cvt.u32.u64 %0, t; }" : "=r"(a) : "l"(p));
    return a;
}
static __device__ __forceinline__ void cp16(uint32_t dst, const void* src) {
    asm volatile("cp.async.cg.shared.global [%0], [%1], 16;" :: "r"(dst), "l"(src));
}
static __device__ __forceinline__ void cp_commit() {
    asm volatile("cp.async.commit_group;" ::: "memory");
}
template <int N> static __device__ __forceinline__ void cp_wait() {
    asm volatile("cp.async.wait_group %0;" :: "n"(N) : "memory");
}
#define LDSM4(r0, r1, r2, r3, addr) \
    asm volatile("ldmatrix.sync.aligned.m8n8.x4.shared.b16 {%0,%1,%2,%3}, [%4];" \
                 : "=r"(r0), "=r"(r1), "=r"(r2), "=r"(r3) : "r"(addr))
#define MMA16816(c, a, b) \
    asm volatile("mma.sync.aligned.m16n8k16.row.col.f32.bf16.bf16.f32 " \
                 "{%0,%1,%2,%3}, {%4,%5,%6,%7}, {%8,%9}, {%0,%1,%2,%3};" \
                 : "+f"((c)[0]), "+f"((c)[1]), "+f"((c)[2]), "+f"((c)[3]) \
                 : "r"((a)[0]), "r"((a)[1]), "r"((a)[2]), "r"((a)[3]), \
                   "r"((b)[0]), "r"((b)[1]))

static __device__ __forceinline__ void relu_params(float v, float r,
                                                   float& s, float& t, float& vn) {
    float u = v + r;
    float l = v - r;
    if (u <= 0.f)       { s = 0.f; t = 0.f; vn = 0.f; }
    else if (l < 0.f)   { float slope = u / (u - l); float term = (1.f - slope) * u * 0.5f;
                          s = slope; t = term; vn = slope * v + term; }
    else                { s = 1.f; t = 0.f; vn = v; }
}
static __device__ __forceinline__ void split_hl(float x, __nv_bfloat16& h, __nv_bfloat16& l) {
    h = __float2bfloat16_rn(x);
    l = __float2bfloat16_rn(x - __bfloat162float(h));
}

// ---- K0 ----
__global__ void k0_init(const float* __restrict__ in) {
    int j = threadIdx.x;
    float x  = in[j];
    float up = fminf(x + C_EPS, 1.f);
    float lo = fmaxf(x - C_EPS, 0.f);
    float val = up + lo;
    g_v0[j] = (val - C_MEAN) / C_SIGMA;
    g_d[j]  = up / C_SIGMA;
}

// ---- K1 ----
__global__ void k1_layer1(const float* __restrict__ W1, const float* __restrict__ b1) {
    int row  = blockIdx.x * 8 + (threadIdx.x >> 5);
    int lane = threadIdx.x & 31;
    const float* w = W1 + (size_t)row * DD;
    float sv = 0.f, sr = 0.f;
    #pragma unroll
    for (int j = lane * 4; j < DD; j += 128) {
        float4 wv = *(const float4*)(w + j);
        float4 v  = *(const float4*)(g_v0 + j);
        float4 dd = *(const float4*)(g_d + j);
        sv += wv.x * v.x + wv.y * v.y + wv.z * v.z + wv.w * v.w;
        sr += fabsf(wv.x) * dd.x + fabsf(wv.y) * dd.y
            + fabsf(wv.z) * dd.z + fabsf(wv.w) * dd.w;
    }
    #pragma unroll
    for (int o = 16; o; o >>= 1) {
        sv += __shfl_xor_sync(0xffffffffu, sv, o);
        sr += __shfl_xor_sync(0xffffffffu, sr, o);
    }
    if (lane == 0) {
        float v = sv + b1[row];
        float s, t, vn;
        relu_params(v, sr, s, t, vn);
        g_s1[row] = s; g_t1[row] = t; g_v1p[row] = vn;
    }
}

// ---- K2a: split W2 into bf16 hi/lo ----
__global__ void k2a_convW2(const float* __restrict__ W2) {
    size_t i4 = (size_t)blockIdx.x * blockDim.x + threadIdx.x;
    float4 x = *(const float4*)(W2 + i4 * 4);
    __nv_bfloat16 h0,h1,h2,h3,l0,l1,l2,l3;
    split_hl(x.x,h0,l0); split_hl(x.y,h1,l1); split_hl(x.z,h2,l2); split_hl(x.w,h3,l3);
    ushort4 hh = make_ushort4(__bfloat16_as_ushort(h0), __bfloat16_as_ushort(h1),
                              __bfloat16_as_ushort(h2), __bfloat16_as_ushort(h3));
    ushort4 ll = make_ushort4(__bfloat16_as_ushort(l0), __bfloat16_as_ushort(l1),
                              __bfloat16_as_ushort(l2), __bfloat16_as_ushort(l3));
    *(ushort4*)((unsigned short*)g_W2h + i4 * 4) = hh;
    *(ushort4*)((unsigned short*)g_W2l + i4 * 4) = ll;
}

// ---- K2b: BaugT rows 0..1023 ----
__global__ void k2b_buildBT(const float* __restrict__ W1) {
    __shared__ float ts[32][33];
    int k0 = blockIdx.x * 32;
    int j0 = blockIdx.y * 32;
    int tx = threadIdx.x & 31, ty = threadIdx.x >> 5;
    #pragma unroll
    for (int r = 0; r < 4; r++) {
        int k = k0 + ty + r * 8;
        ts[ty + r * 8][tx] = W1[(size_t)k * DD + j0 + tx] * g_s1[k];
    }
    __syncthreads();
    #pragma unroll
    for (int r = 0; r < 4; r++) {
        int j = j0 + ty + r * 8;
        float x = ts[tx][ty + r * 8] * g_d[j];
        __nv_bfloat16 h, l; split_hl(x, h, l);
        g_BTh[(size_t)j * HH + k0 + tx] = h;
        g_BTl[(size_t)j * HH + k0 + tx] = l;
    }
}

// ---- K2c: BaugT rows 1024..1151 ----
__global__ void k2c_tailBT() {
    int idx = blockIdx.x * blockDim.x + threadIdx.x;
    int rl = idx >> 12;
    int k  = idx & 4095;
    float x = (rl == 0) ? g_t1[k] : (rl == 1 ? g_v1p[k] : 0.f);
    __nv_bfloat16 h, l; split_hl(x, h, l);
    g_BTh[(size_t)(DD + rl) * HH + k] = h;
    g_BTl[(size_t)(DD + rl) * HH + k] = l;
}

// ================== K3: mma.sync bf16 GEMM, merged-split stages ==================
// CTA tile 256(M) x 128(N), BK=32. 8 warps: 4(M) x 2(N), warp tile 64x64.
// Stage (48KB) = Ah[256x32]@0 | Al@16K | Bh[128x32]@32K | Bl@40K. 3-stage ring.
#define NKG 128
#define STG_BYTES 49152
#define STG_AL 16384
#define STG_BH 32768
#define STG_BL 40960
#define K3_SMEM (3 * STG_BYTES)

__global__ __launch_bounds__(256, 1) void k3_mma() {
    extern __shared__ __align__(1024) unsigned char sm[];
    const int tid  = threadIdx.x;
    const int lane = tid & 31;
    const int wid  = tid >> 5;
    const int warp_m = wid & 3;        // M offset 64*warp_m
    const int warp_n = wid >> 2;       // N offset 64*warp_n
    const int i0 = blockIdx.y * 256;
    const int j0 = blockIdx.x * 128;
    const uint32_t sbase = smem_u32(sm);

    // ldmatrix lane offsets
    const int ra = (lane & 7) + (((lane >> 3) & 1) << 3);
    const int ha = lane >> 4;
    const int rb = (lane & 7) + ((lane >> 4) << 3);
    const int hb = (lane >> 3) & 1;
    uint32_t offA[4][2], offB[4][2];
    #pragma unroll
    for (int mf = 0; mf < 4; mf++)
        #pragma unroll
        for (int kk = 0; kk < 2; kk++) {
            int row = warp_m * 64 + mf * 16 + ra;
            int c   = kk * 2 + ha;
            offA[mf][kk] = row * 64 + ((c ^ ((row >> 1) & 3)) << 4);
        }
    #pragma unroll
    for (int nf4 = 0; nf4 < 4; nf4++)
        #pragma unroll
        for (int kk = 0; kk < 2; kk++) {
            int row = warp_n * 64 + nf4 * 16 + rb;
            int c   = kk * 2 + hb;
            offB[nf4][kk] = row * 64 + ((c ^ ((row >> 1) & 3)) << 4);
        }

    // fill: stage <- {Ah, Al, Bh, Bl} for k-group kg. 12 cp16/thread.
    const int f_c = tid & 3;
    auto fill = [&](int stage, int kg) {
        const uint32_t base = sbase + stage * STG_BYTES;
        const int kgo = kg * 32;
        #pragma unroll
        for (int s = 0; s < 4; s++) {
            int q = s * 256 + tid;
            int r = q >> 2, c = q & 3;
            uint32_t sw = r * 64 + ((c ^ ((r >> 1) & 3)) << 4);
            const size_t go = (size_t)(i0 + r) * HH + kgo + c * 8;
            cp16(base + sw,          g_W2h + go);
            cp16(base + STG_AL + sw, g_W2l + go);
        }
        #pragma unroll
        for (int s = 0; s < 2; s++) {
            int q = s * 256 + tid;
            int r = q >> 2, c = q & 3;
            uint32_t sw = r * 64 + ((c ^ ((r >> 1) & 3)) << 4);
            const size_t go = (size_t)(j0 + r) * HH + kgo + c * 8;
            cp16(base + STG_BH + sw, g_BTh + go);
            cp16(base + STG_BL + sw, g_BTl + go);
        }
        cp_commit();
    };

    float acc[4][8][4];
    #pragma unroll
    for (int mf = 0; mf < 4; mf++)
        #pragma unroll
        for (int nf = 0; nf < 8; nf++)
            #pragma unroll
            for (int q = 0; q < 4; q++) acc[mf][nf][q] = 0.f;

    fill(0, 0);
    fill(1, 1);

    for (int kg = 0; kg < NKG; ++kg) {
        cp_wait<1>();
        __syncthreads();
        if (kg + 2 < NKG) fill((kg + 2) % 3, kg + 2);
        const uint32_t base = sbase + (kg % 3) * STG_BYTES;
        // 3 passes: (Ah,Bh), (Ah,Bl), (Al,Bh)
        #pragma unroll
        for (int pass = 0; pass < 3; ++pass) {
            const uint32_t abase = base + (pass == 2 ? STG_AL : 0u);
            const uint32_t bbase = base + (pass == 1 ? STG_BL : STG_BH);
            #pragma unroll
            for (int kk = 0; kk < 2; kk++) {
                uint32_t a[4][4], b[8][2];
                #pragma unroll
                for (int mf = 0; mf < 4; mf++)
                    LDSM4(a[mf][0], a[mf][1], a[mf][2], a[mf][3], abase + offA[mf][kk]);
                #pragma unroll
                for (int nf4 = 0; nf4 < 4; nf4++) {
                    uint32_t r0, r1, r2, r3;
                    LDSM4(r0, r1, r2, r3, bbase + offB[nf4][kk]);
                    b[nf4 * 2][0] = r0;     b[nf4 * 2][1] = r1;
                    b[nf4 * 2 + 1][0] = r2; b[nf4 * 2 + 1][1] = r3;
                }
                #pragma unroll
                for (int mf = 0; mf < 4; mf++)
                    #pragma unroll
                    for (int nf = 0; nf < 8; nf++)
                        MMA16816(acc[mf][nf], a[mf], b[nf]);
            }
        }
    }

    // epilogue
    const int er = lane >> 2;
    const int ec = (lane & 3) * 2;
    #pragma unroll
    for (int mf = 0; mf < 4; mf++) {
        #pragma unroll
        for (int nf = 0; nf < 8; nf++) {
            int row = i0 + warp_m * 64 + mf * 16 + er;
            int col = j0 + warp_n * 64 + nf * 8 + ec;
            *(float2*)(g_E2 + (size_t)row * SB + col)       = make_float2(acc[mf][nf][0], acc[mf][nf][1]);
            *(float2*)(g_E2 + (size_t)(row + 8) * SB + col) = make_float2(acc[mf][nf][2], acc[mf][nf][3]);
        }
    }
}

// ---- K4 ----
__global__ void k4_relu2(const float* __restrict__ b2) {
    int row  = blockIdx.x * 8 + (threadIdx.x >> 5);
    int lane = threadIdx.x & 31;
    const float* e = g_E2 + (size_t)row * SB;
    float sr = 0.f;
    #pragma unroll 4
    for (int j = lane * 4; j < DD; j += 128) {
        float4 x = *(const float4*)(e + j);
        sr += fabsf(x.x) + fabsf(x.y) + fabsf(x.z) + fabsf(x.w);
    }
    #pragma unroll
    for (int o = 16; o; o >>= 1) sr += __shfl_xor_sync(0xffffffffu, sr, o);
    if (lane == 0) {
        sr += fabsf(e[DD]);
        float v = e[DD + 1] + b2[row];
        float s, t, vn;
        relu_params(v, sr, s, t, vn);
        g_s2[row] = s; g_t2[row] = t; g_v2p[row] = vn;
    }
}

// ---- K5 ----
__global__ void k5_e3(const float* __restrict__ W3) {
    __shared__ float w3s[OO][256];
    __shared__ float s2s[256];
    const int jt = blockIdx.x, ks = blockIdx.y;
    const int k0 = ks * 256;
    const int tid = threadIdx.x;

    for (int idx = tid; idx < OO * 256; idx += 128) {
        int i = idx >> 8, kk = idx & 255;
        w3s[i][kk] = W3[(size_t)i * HH + k0 + kk];
    }
    for (int kk = tid; kk < 256; kk += 128) s2s[kk] = g_s2[k0 + kk];
    __syncthreads();

    const int j = jt * 128 + tid;
    float acc[OO];
    #pragma unroll
    for (int i = 0; i < OO; i++) acc[i] = 0.f;

    if (j < 1025) {
        const float* e = g_E2 + (size_t)k0 * SB + j;
        for (int kk = 0; kk < 256; ++kk) {
            float bval = s2s[kk] * e[(size_t)kk * SB];
            #pragma unroll
            for (int i = 0; i < OO; i++) acc[i] += w3s[i][kk] * bval;
        }
    } else if (j == 1025) {
        for (int kk = 0; kk < 256; ++kk) {
            float bval = g_t2[k0 + kk];
            #pragma unroll
            for (int i = 0; i < OO; i++) acc[i] += w3s[i][kk] * bval;
        }
    } else if (j == 1026) {
        for (int kk = 0; kk < 256; ++kk) {
            float bval = g_v2p[k0 + kk];
            #pragma unroll
            for (int i = 0; i < OO; i++) acc[i] += w3s[i][kk] * bval;
        }
    }
    if (j < NC3) {
        #pragma unroll
        for (int i = 0; i < OO; i++)
            g_E3p[((size_t)ks * OO + i) * SE3 + j] = acc[i];
    }
}

// ---- K6 ----
__global__ void k6_final(const float* __restrict__ b3, float* __restrict__ out) {
    const int i = blockIdx.x;
    const int tid = threadIdx.x;
    __shared__ float red[256];
    __shared__ float vsh;
    float racc = 0.f;
    for (int j = tid; j < NC3; j += 256) {
        float s = 0.f;
        #pragma unroll
        for (int ks = 0; ks < KS3; ks++) s += g_E3p[((size_t)ks * OO + i) * SE3 + j];
        if (j < 1026) racc += fabsf(s);
        else          vsh = s + b3[i];
    }
    red[tid] = racc;
    __syncthreads();
    for (int o = 128; o; o >>= 1) {
        if (tid < o) red[tid] += red[tid + o];
        __syncthreads();
    }
    if (tid == 0) {
        float v = vsh, r = red[0];
        out[i]      = v + r;
        out[10 + i] = v - r;
    }
}

extern "C" void kernel_launch(void* const* d_in, const int* in_sizes, int n_in,
                              void* d_out, int out_size) {
    const float* inputs = (const float*)d_in[0];
    const float* W1     = (const float*)d_in[1];
    const float* b1     = (const float*)d_in[2];
    const float* W2     = (const float*)d_in[3];
    const float* b2     = (const float*)d_in[4];
    const float* W3     = (const float*)d_in[5];
    const float* b3     = (const float*)d_in[6];
    float* out = (float*)d_out;

    cudaFuncSetAttribute(k3_mma, cudaFuncAttributeMaxDynamicSharedMemorySize, K3_SMEM);

    k0_init<<<1, DD>>>(inputs);
    k1_layer1<<<HH / 8, 256>>>(W1, b1);
    k2a_convW2<<<((size_t)HH * HH / 4) / 256, 256>>>(W2);
    dim3 g2b(HH / 32, DD / 32);
    k2b_buildBT<<<g2b, 256>>>(W1);
    k2c_tailBT<<<(128 * HH) / 256, 256>>>();
    dim3 g3(SB / 128, HH / 256);           // 9 x 16 = 144 CTAs (one wave)
    k3_mma<<<g3, 256, K3_SMEM>>>();
    k4_relu2<<<HH / 8, 256>>>(b2);
    dim3 g5(9, KS3);
    k5_e3<<<g5, 128>>>(W3);
    k6_final<<<OO, 256>>>(b3, out);
}

// round 6
// speedup vs baseline: 3.0243x; 1.0153x over previous
#include <cuda_runtime.h>
#include <cuda_bf16.h>
#include <cstdint>

// Zonotope propagation: D=1024 -> H=4096 -> H=4096 -> O=10
// Heavy op: E2 = W2 @ Baug (4096x4096 @ 4096x1152), via mma.sync bf16 with a
// 3-way hi/lo split: AhBh + AhBl + AlBh (fp32 accumulate) -> ~1e-5 accuracy.
// R5: register-cached fragments across split passes (16 LDSM4/kk instead of 24).

#define DD 1024
#define HH 4096
#define OO 10
#define SB 1152
#define NC3 1027
#define SE3 1056
#define KS3 16

#define C_EPS   0.01f
#define C_MEAN  0.1307f
#define C_SIGMA 0.3081f

// ---- device scratch ----
__device__ float g_v0[DD];
__device__ float g_d[DD];
__device__ float g_s1[HH];
__device__ float g_t1[HH];
__device__ float g_v1p[HH];
__device__ __nv_bfloat16 g_W2h[(size_t)HH * HH];
__device__ __nv_bfloat16 g_W2l[(size_t)HH * HH];
__device__ __nv_bfloat16 g_BTh[(size_t)SB * HH];
__device__ __nv_bfloat16 g_BTl[(size_t)SB * HH];
__device__ float g_E2[(size_t)HH * SB];
__device__ float g_s2[HH];
__device__ float g_t2[HH];
__device__ float g_v2p[HH];
__device__ float g_E3p[KS3 * OO * SE3];

// ================= PTX helpers =================
static __device__ __forceinline__ uint32_t smem_u32(const void* p) {
    uint32_t a;
    asm("{ .reg .u64 t; cvta.to.shared.u64 t, %1; cvt.u32.u64 %0, t; }" : "=r"(a) : "l"(p));
    return a;
}
static __device__ __forceinline__ void cp16(uint32_t dst, const void* src) {
    asm volatile("cp.async.cg.shared.global [%0], [%1], 16;" :: "r"(dst), "l"(src));
}
static __device__ __forceinline__ void cp_commit() {
    asm volatile("cp.async.commit_group;" ::: "memory");
}
template <int N> static __device__ __forceinline__ void cp_wait() {
    asm volatile("cp.async.wait_group %0;" :: "n"(N) : "memory");
}
#define LDSM4(r0, r1, r2, r3, addr) \
    asm volatile("ldmatrix.sync.aligned.m8n8.x4.shared.b16 {%0,%1,%2,%3}, [%4];" \
                 : "=r"(r0), "=r"(r1), "=r"(r2), "=r"(r3) : "r"(addr))
#define MMA16816(c, a, b) \
    asm volatile("mma.sync.aligned.m16n8k16.row.col.f32.bf16.bf16.f32 " \
                 "{%0,%1,%2,%3}, {%4,%5,%6,%7}, {%8,%9}, {%0,%1,%2,%3};" \
                 : "+f"((c)[0]), "+f"((c)[1]), "+f"((c)[2]), "+f"((c)[3]) \
                 : "r"((a)[0]), "r"((a)[1]), "r"((a)[2]), "r"((a)[3]), \
                   "r"((b)[0]), "r"((b)[1]))

static __device__ __forceinline__ void relu_params(float v, float r,
                                                   float& s, float& t, float& vn) {
    float u = v + r;
    float l = v - r;
    if (u <= 0.f)       { s = 0.f; t = 0.f; vn = 0.f; }
    else if (l < 0.f)   { float slope = u / (u - l); float term = (1.f - slope) * u * 0.5f;
                          s = slope; t = term; vn = slope * v + term; }
    else                { s = 1.f; t = 0.f; vn = v; }
}
static __device__ __forceinline__ void split_hl(float x, __nv_bfloat16& h, __nv_bfloat16& l) {
    h = __float2bfloat16_rn(x);
    l = __float2bfloat16_rn(x - __bfloat162float(h));
}

// ---- K0 ----
__global__ void k0_init(const float* __restrict__ in) {
    int j = threadIdx.x;
    float x  = in[j];
    float up = fminf(x + C_EPS, 1.f);
    float lo = fmaxf(x - C_EPS, 0.f);
    float val = up + lo;
    g_v0[j] = (val - C_MEAN) / C_SIGMA;
    g_d[j]  = up / C_SIGMA;
}

// ---- K1 ----
__global__ void k1_layer1(const float* __restrict__ W1, const float* __restrict__ b1) {
    int row  = blockIdx.x * 8 + (threadIdx.x >> 5);
    int lane = threadIdx.x & 31;
    const float* w = W1 + (size_t)row * DD;
    float sv = 0.f, sr = 0.f;
    #pragma unroll
    for (int j = lane * 4; j < DD; j += 128) {
        float4 wv = *(const float4*)(w + j);
        float4 v  = *(const float4*)(g_v0 + j);
        float4 dd = *(const float4*)(g_d + j);
        sv += wv.x * v.x + wv.y * v.y + wv.z * v.z + wv.w * v.w;
        sr += fabsf(wv.x) * dd.x + fabsf(wv.y) * dd.y
            + fabsf(wv.z) * dd.z + fabsf(wv.w) * dd.w;
    }
    #pragma unroll
    for (int o = 16; o; o >>= 1) {
        sv += __shfl_xor_sync(0xffffffffu, sv, o);
        sr += __shfl_xor_sync(0xffffffffu, sr, o);
    }
    if (lane == 0) {
        float v = sv + b1[row];
        float s, t, vn;
        relu_params(v, sr, s, t, vn);
        g_s1[row] = s; g_t1[row] = t; g_v1p[row] = vn;
    }
}

// ---- K2a: split W2 into bf16 hi/lo ----
__global__ void k2a_convW2(const float* __restrict__ W2) {
    size_t i4 = (size_t)blockIdx.x * blockDim.x + threadIdx.x;
    float4 x = *(const float4*)(W2 + i4 * 4);
    __nv_bfloat16 h0,h1,h2,h3,l0,l1,l2,l3;
    split_hl(x.x,h0,l0); split_hl(x.y,h1,l1); split_hl(x.z,h2,l2); split_hl(x.w,h3,l3);
    ushort4 hh = make_ushort4(__bfloat16_as_ushort(h0), __bfloat16_as_ushort(h1),
                              __bfloat16_as_ushort(h2), __bfloat16_as_ushort(h3));
    ushort4 ll = make_ushort4(__bfloat16_as_ushort(l0), __bfloat16_as_ushort(l1),
                              __bfloat16_as_ushort(l2), __bfloat16_as_ushort(l3));
    *(ushort4*)((unsigned short*)g_W2h + i4 * 4) = hh;
    *(ushort4*)((unsigned short*)g_W2l + i4 * 4) = ll;
}

// ---- K2b: BaugT rows 0..1023 ----
__global__ void k2b_buildBT(const float* __restrict__ W1) {
    __shared__ float ts[32][33];
    int k0 = blockIdx.x * 32;
    int j0 = blockIdx.y * 32;
    int tx = threadIdx.x & 31, ty = threadIdx.x >> 5;
    #pragma unroll
    for (int r = 0; r < 4; r++) {
        int k = k0 + ty + r * 8;
        ts[ty + r * 8][tx] = W1[(size_t)k * DD + j0 + tx] * g_s1[k];
    }
    __syncthreads();
    #pragma unroll
    for (int r = 0; r < 4; r++) {
        int j = j0 + ty + r * 8;
        float x = ts[tx][ty + r * 8] * g_d[j];
        __nv_bfloat16 h, l; split_hl(x, h, l);
        g_BTh[(size_t)j * HH + k0 + tx] = h;
        g_BTl[(size_t)j * HH + k0 + tx] = l;
    }
}

// ---- K2c: BaugT rows 1024..1151 ----
__global__ void k2c_tailBT() {
    int idx = blockIdx.x * blockDim.x + threadIdx.x;
    int rl = idx >> 12;
    int k  = idx & 4095;
    float x = (rl == 0) ? g_t1[k] : (rl == 1 ? g_v1p[k] : 0.f);
    __nv_bfloat16 h, l; split_hl(x, h, l);
    g_BTh[(size_t)(DD + rl) * HH + k] = h;
    g_BTl[(size_t)(DD + rl) * HH + k] = l;
}

// ================== K3: mma.sync bf16 GEMM, reg-cached split passes ==========
// CTA tile 256(M) x 128(N), BK=32. 8 warps: 4(M) x 2(N), warp tile 64x64.
// Stage (48KB) = Ah[256x32]@0 | Al@16K | Bh[128x32]@32K | Bl@40K. 3-stage ring.
#define NKG 128
#define STG_BYTES 49152
#define STG_AL 16384
#define STG_BH 32768
#define STG_BL 40960
#define K3_SMEM (3 * STG_BYTES)

__global__ __launch_bounds__(256, 1) void k3_mma() {
    extern __shared__ __align__(1024) unsigned char sm[];
    const int tid  = threadIdx.x;
    const int lane = tid & 31;
    const int wid  = tid >> 5;
    const int warp_m = wid & 3;
    const int warp_n = wid >> 2;
    const int i0 = blockIdx.y * 256;
    const int j0 = blockIdx.x * 128;
    const uint32_t sbase = smem_u32(sm);

    const int ra = (lane & 7) + (((lane >> 3) & 1) << 3);
    const int ha = lane >> 4;
    const int rb = (lane & 7) + ((lane >> 4) << 3);
    const int hb = (lane >> 3) & 1;
    uint32_t offA[4][2], offB[4][2];
    #pragma unroll
    for (int mf = 0; mf < 4; mf++)
        #pragma unroll
        for (int kk = 0; kk < 2; kk++) {
            int row = warp_m * 64 + mf * 16 + ra;
            int c   = kk * 2 + ha;
            offA[mf][kk] = row * 64 + ((c ^ ((row >> 1) & 3)) << 4);
        }
    #pragma unroll
    for (int nf4 = 0; nf4 < 4; nf4++)
        #pragma unroll
        for (int kk = 0; kk < 2; kk++) {
            int row = warp_n * 64 + nf4 * 16 + rb;
            int c   = kk * 2 + hb;
            offB[nf4][kk] = row * 64 + ((c ^ ((row >> 1) & 3)) << 4);
        }

    auto fill = [&](int stage, int kg) {
        const uint32_t base = sbase + stage * STG_BYTES;
        const int kgo = kg * 32;
        #pragma unroll
        for (int s = 0; s < 4; s++) {
            int q = s * 256 + tid;
            int r = q >> 2, c = q & 3;
            uint32_t sw = r * 64 + ((c ^ ((r >> 1) & 3)) << 4);
            const size_t go = (size_t)(i0 + r) * HH + kgo + c * 8;
            cp16(base + sw,          g_W2h + go);
            cp16(base + STG_AL + sw, g_W2l + go);
        }
        #pragma unroll
        for (int s = 0; s < 2; s++) {
            int q = s * 256 + tid;
            int r = q >> 2, c = q & 3;
            uint32_t sw = r * 64 + ((c ^ ((r >> 1) & 3)) << 4);
            const size_t go = (size_t)(j0 + r) * HH + kgo + c * 8;
            cp16(base + STG_BH + sw, g_BTh + go);
            cp16(base + STG_BL + sw, g_BTl + go);
        }
        cp_commit();
    };

    float acc[4][8][4];
    #pragma unroll
    for (int mf = 0; mf < 4; mf++)
        #pragma unroll
        for (int nf = 0; nf < 8; nf++)
            #pragma unroll
            for (int q = 0; q < 4; q++) acc[mf][nf][q] = 0.f;

    fill(0, 0);
    fill(1, 1);

    for (int kg = 0; kg < NKG; ++kg) {
        cp_wait<1>();
        __syncthreads();
        if (kg + 2 < NKG) fill((kg + 2) % 3, kg + 2);
        const uint32_t base = sbase + (kg % 3) * STG_BYTES;
        #pragma unroll
        for (int kk = 0; kk < 2; kk++) {
            uint32_t a[4][4], bh[8][2], bl[8][2];
            // load Ah, Bh, Bl fragments once
            #pragma unroll
            for (int mf = 0; mf < 4; mf++)
                LDSM4(a[mf][0], a[mf][1], a[mf][2], a[mf][3], base + offA[mf][kk]);
            #pragma unroll
            for (int nf4 = 0; nf4 < 4; nf4++) {
                uint32_t r0, r1, r2, r3;
                LDSM4(r0, r1, r2, r3, base + STG_BH + offB[nf4][kk]);
                bh[nf4 * 2][0] = r0;     bh[nf4 * 2][1] = r1;
                bh[nf4 * 2 + 1][0] = r2; bh[nf4 * 2 + 1][1] = r3;
            }
            #pragma unroll
            for (int nf4 = 0; nf4 < 4; nf4++) {
                uint32_t r0, r1, r2, r3;
                LDSM4(r0, r1, r2, r3, base + STG_BL + offB[nf4][kk]);
                bl[nf4 * 2][0] = r0;     bl[nf4 * 2][1] = r1;
                bl[nf4 * 2 + 1][0] = r2; bl[nf4 * 2 + 1][1] = r3;
            }
            // pass 0: Ah * Bh
            #pragma unroll
            for (int mf = 0; mf < 4; mf++)
                #pragma unroll
                for (int nf = 0; nf < 8; nf++)
                    MMA16816(acc[mf][nf], a[mf], bh[nf]);
            // pass 1: Ah * Bl
            #pragma unroll
            for (int mf = 0; mf < 4; mf++)
                #pragma unroll
                for (int nf = 0; nf < 8; nf++)
                    MMA16816(acc[mf][nf], a[mf], bl[nf]);
            // reload A with Al, pass 2: Al * Bh
            #pragma unroll
            for (int mf = 0; mf < 4; mf++)
                LDSM4(a[mf][0], a[mf][1], a[mf][2], a[mf][3], base + STG_AL + offA[mf][kk]);
            #pragma unroll
            for (int mf = 0; mf < 4; mf++)
                #pragma unroll
                for (int nf = 0; nf < 8; nf++)
                    MMA16816(acc[mf][nf], a[mf], bh[nf]);
        }
    }

    // epilogue
    const int er = lane >> 2;
    const int ec = (lane & 3) * 2;
    #pragma unroll
    for (int mf = 0; mf < 4; mf++) {
        #pragma unroll
        for (int nf = 0; nf < 8; nf++) {
            int row = i0 + warp_m * 64 + mf * 16 + er;
            int col = j0 + warp_n * 64 + nf * 8 + ec;
            *(float2*)(g_E2 + (size_t)row * SB + col)       = make_float2(acc[mf][nf][0], acc[mf][nf][1]);
            *(float2*)(g_E2 + (size_t)(row + 8) * SB + col) = make_float2(acc[mf][nf][2], acc[mf][nf][3]);
        }
    }
}

// ---- K4 ----
__global__ void k4_relu2(const float* __restrict__ b2) {
    int row  = blockIdx.x * 8 + (threadIdx.x >> 5);
    int lane = threadIdx.x & 31;
    const float* e = g_E2 + (size_t)row * SB;
    float sr = 0.f;
    #pragma unroll 4
    for (int j = lane * 4; j < DD; j += 128) {
        float4 x = *(const float4*)(e + j);
        sr += fabsf(x.x) + fabsf(x.y) + fabsf(x.z) + fabsf(x.w);
    }
    #pragma unroll
    for (int o = 16; o; o >>= 1) sr += __shfl_xor_sync(0xffffffffu, sr, o);
    if (lane == 0) {
        sr += fabsf(e[DD]);
        float v = e[DD + 1] + b2[row];
        float s, t, vn;
        relu_params(v, sr, s, t, vn);
        g_s2[row] = s; g_t2[row] = t; g_v2p[row] = vn;
    }
}

// ---- K5 ----
__global__ void k5_e3(const float* __restrict__ W3) {
    __shared__ float w3s[OO][256];
    __shared__ float s2s[256];
    const int jt = blockIdx.x, ks = blockIdx.y;
    const int k0 = ks * 256;
    const int tid = threadIdx.x;

    for (int idx = tid; idx < OO * 256; idx += 128) {
        int i = idx >> 8, kk = idx & 255;
        w3s[i][kk] = W3[(size_t)i * HH + k0 + kk];
    }
    for (int kk = tid; kk < 256; kk += 128) s2s[kk] = g_s2[k0 + kk];
    __syncthreads();

    const int j = jt * 128 + tid;
    float acc[OO];
    #pragma unroll
    for (int i = 0; i < OO; i++) acc[i] = 0.f;

    if (j < 1025) {
        const float* e = g_E2 + (size_t)k0 * SB + j;
        for (int kk = 0; kk < 256; ++kk) {
            float bval = s2s[kk] * e[(size_t)kk * SB];
            #pragma unroll
            for (int i = 0; i < OO; i++) acc[i] += w3s[i][kk] * bval;
        }
    } else if (j == 1025) {
        for (int kk = 0; kk < 256; ++kk) {
            float bval = g_t2[k0 + kk];
            #pragma unroll
            for (int i = 0; i < OO; i++) acc[i] += w3s[i][kk] * bval;
        }
    } else if (j == 1026) {
        for (int kk = 0; kk < 256; ++kk) {
            float bval = g_v2p[k0 + kk];
            #pragma unroll
            for (int i = 0; i < OO; i++) acc[i] += w3s[i][kk] * bval;
        }
    }
    if (j < NC3) {
        #pragma unroll
        for (int i = 0; i < OO; i++)
            g_E3p[((size_t)ks * OO + i) * SE3 + j] = acc[i];
    }
}

// ---- K6 ----
__global__ void k6_final(const float* __restrict__ b3, float* __restrict__ out) {
    const int i = blockIdx.x;
    const int tid = threadIdx.x;
    __shared__ float red[256];
    __shared__ float vsh;
    float racc = 0.f;
    for (int j = tid; j < NC3; j += 256) {
        float s = 0.f;
        #pragma unroll
        for (int ks = 0; ks < KS3; ks++) s += g_E3p[((size_t)ks * OO + i) * SE3 + j];
        if (j < 1026) racc += fabsf(s);
        else          vsh = s + b3[i];
    }
    red[tid] = racc;
    __syncthreads();
    for (int o = 128; o; o >>= 1) {
        if (tid < o) red[tid] += red[tid + o];
        __syncthreads();
    }
    if (tid == 0) {
        float v = vsh, r = red[0];
        out[i]      = v + r;
        out[10 + i] = v - r;
    }
}

extern "C" void kernel_launch(void* const* d_in, const int* in_sizes, int n_in,
                              void* d_out, int out_size) {
    const float* inputs = (const float*)d_in[0];
    const float* W1     = (const float*)d_in[1];
    const float* b1     = (const float*)d_in[2];
    const float* W2     = (const float*)d_in[3];
    const float* b2     = (const float*)d_in[4];
    const float* W3     = (const float*)d_in[5];
    const float* b3     = (const float*)d_in[6];
    float* out = (float*)d_out;

    cudaFuncSetAttribute(k3_mma, cudaFuncAttributeMaxDynamicSharedMemorySize, K3_SMEM);

    k0_init<<<1, DD>>>(inputs);
    k1_layer1<<<HH / 8, 256>>>(W1, b1);
    k2a_convW2<<<((size_t)HH * HH / 4) / 256, 256>>>(W2);
    dim3 g2b(HH / 32, DD / 32);
    k2b_buildBT<<<g2b, 256>>>(W1);
    k2c_tailBT<<<(128 * HH) / 256, 256>>>();
    dim3 g3(SB / 128, HH / 256);           // 9 x 16 = 144 CTAs (one wave)
    k3_mma<<<g3, 256, K3_SMEM>>>();
    k4_relu2<<<HH / 8, 256>>>(b2);
    dim3 g5(9, KS3);
    k5_e3<<<g5, 128>>>(W3);
    k6_final<<<OO, 256>>>(b3, out);
}

// round 7
// speedup vs baseline: 3.2459x; 1.0733x over previous
#include <cuda_runtime.h>
#include <cuda_bf16.h>
#include <cstdint>

// Zonotope propagation: D=1024 -> H=4096 -> H=4096 -> O=10
// Heavy op: E2 = W2 @ Baug via mma.sync bf16, 3-way hi/lo split (AhBh+AhBl+AlBh).
// R6: drop zero-pad columns (N=1024; t1/v1p cols via side matvec k3b),
//     128x128 tiles, k-split x4 -> 1024 CTAs @ occ 2 (load balance 402->352 MMAC/SM),
//     stream-forked prep (k2a, k3b) overlapped via capture-legal events.

#define DD 1024
#define HH 4096
#define OO 10
#define NE 1024          // E2 eps columns (exact, no pad)
#define NC3 1027
#define SE3 1056
#define KS3 16
#define KSPL 4           // k-split factor for k3

#define C_EPS   0.01f
#define C_MEAN  0.1307f
#define C_SIGMA 0.3081f

// ---- device scratch ----
__device__ float g_v0[DD];
__device__ float g_d[DD];
__device__ float g_s1[HH];
__device__ float g_t1[HH];
__device__ float g_v1p[HH];
__device__ __nv_bfloat16 g_W2h[(size_t)HH * HH];
__device__ __nv_bfloat16 g_W2l[(size_t)HH * HH];
__device__ __nv_bfloat16 g_BTh[(size_t)NE * HH];
__device__ __nv_bfloat16 g_BTl[(size_t)NE * HH];
__device__ float g_E2p[(size_t)KSPL * HH * NE];   // 4 partial buffers, 67MB
__device__ float g_tcol[HH];
__device__ float g_vcol[HH];
__device__ float g_s2[HH];
__device__ float g_t2[HH];
__device__ float g_v2p[HH];
__device__ float g_E3p[KS3 * OO * SE3];

// ================= PTX helpers =================
static __device__ __forceinline__ uint32_t smem_u32(const void* p) {
    uint32_t a;
    asm("{ .reg .u64 t; cvta.to.shared.u64 t, %1; cvt.u32.u64 %0, t; }" : "=r"(a) : "l"(p));
    return a;
}
static __device__ __forceinline__ void cp16(uint32_t dst, const void* src) {
    asm volatile("cp.async.cg.shared.global [%0], [%1], 16;" :: "r"(dst), "l"(src));
}
static __device__ __forceinline__ void cp_commit() {
    asm volatile("cp.async.commit_group;" ::: "memory");
}
template <int N> static __device__ __forceinline__ void cp_wait() {
    asm volatile("cp.async.wait_group %0;" :: "n"(N) : "memory");
}
#define LDSM4(r0, r1, r2, r3, addr) \
    asm volatile("ldmatrix.sync.aligned.m8n8.x4.shared.b16 {%0,%1,%2,%3}, [%4];" \
                 : "=r"(r0), "=r"(r1), "=r"(r2), "=r"(r3) : "r"(addr))
#define MMA16816(c, a, b) \
    asm volatile("mma.sync.aligned.m16n8k16.row.col.f32.bf16.bf16.f32 " \
                 "{%0,%1,%2,%3}, {%4,%5,%6,%7}, {%8,%9}, {%0,%1,%2,%3};" \
                 : "+f"((c)[0]), "+f"((c)[1]), "+f"((c)[2]), "+f"((c)[3]) \
                 : "r"((a)[0]), "r"((a)[1]), "r"((a)[2]), "r"((a)[3]), \
                   "r"((b)[0]), "r"((b)[1]))

static __device__ __forceinline__ void relu_params(float v, float r,
                                                   float& s, float& t, float& vn) {
    float u = v + r;
    float l = v - r;
    if (u <= 0.f)       { s = 0.f; t = 0.f; vn = 0.f; }
    else if (l < 0.f)   { float slope = u / (u - l); float term = (1.f - slope) * u * 0.5f;
                          s = slope; t = term; vn = slope * v + term; }
    else                { s = 1.f; t = 0.f; vn = v; }
}
static __device__ __forceinline__ void split_hl(float x, __nv_bfloat16& h, __nv_bfloat16& l) {
    h = __float2bfloat16_rn(x);
    l = __float2bfloat16_rn(x - __bfloat162float(h));
}

// ---- K0 ----
__global__ void k0_init(const float* __restrict__ in) {
    int j = threadIdx.x;
    float x  = in[j];
    float up = fminf(x + C_EPS, 1.f);
    float lo = fmaxf(x - C_EPS, 0.f);
    float val = up + lo;
    g_v0[j] = (val - C_MEAN) / C_SIGMA;
    g_d[j]  = up / C_SIGMA;
}

// ---- K1 ----
__global__ void k1_layer1(const float* __restrict__ W1, const float* __restrict__ b1) {
    int row  = blockIdx.x * 8 + (threadIdx.x >> 5);
    int lane = threadIdx.x & 31;
    const float* w = W1 + (size_t)row * DD;
    float sv = 0.f, sr = 0.f;
    #pragma unroll
    for (int j = lane * 4; j < DD; j += 128) {
        float4 wv = *(const float4*)(w + j);
        float4 v  = *(const float4*)(g_v0 + j);
        float4 dd = *(const float4*)(g_d + j);
        sv += wv.x * v.x + wv.y * v.y + wv.z * v.z + wv.w * v.w;
        sr += fabsf(wv.x) * dd.x + fabsf(wv.y) * dd.y
            + fabsf(wv.z) * dd.z + fabsf(wv.w) * dd.w;
    }
    #pragma unroll
    for (int o = 16; o; o >>= 1) {
        sv += __shfl_xor_sync(0xffffffffu, sv, o);
        sr += __shfl_xor_sync(0xffffffffu, sr, o);
    }
    if (lane == 0) {
        float v = sv + b1[row];
        float s, t, vn;
        relu_params(v, sr, s, t, vn);
        g_s1[row] = s; g_t1[row] = t; g_v1p[row] = vn;
    }
}

// ---- K2a: split W2 into bf16 hi/lo (runs on side stream) ----
__global__ void k2a_convW2(const float* __restrict__ W2) {
    size_t i4 = (size_t)blockIdx.x * blockDim.x + threadIdx.x;
    float4 x = *(const float4*)(W2 + i4 * 4);
    __nv_bfloat16 h0,h1,h2,h3,l0,l1,l2,l3;
    split_hl(x.x,h0,l0); split_hl(x.y,h1,l1); split_hl(x.z,h2,l2); split_hl(x.w,h3,l3);
    ushort4 hh = make_ushort4(__bfloat16_as_ushort(h0), __bfloat16_as_ushort(h1),
                              __bfloat16_as_ushort(h2), __bfloat16_as_ushort(h3));
    ushort4 ll = make_ushort4(__bfloat16_as_ushort(l0), __bfloat16_as_ushort(l1),
                              __bfloat16_as_ushort(l2), __bfloat16_as_ushort(l3));
    *(ushort4*)((unsigned short*)g_W2h + i4 * 4) = hh;
    *(ushort4*)((unsigned short*)g_W2l + i4 * 4) = ll;
}

// ---- K2b: BaugT rows 0..1023 ----
__global__ void k2b_buildBT(const float* __restrict__ W1) {
    __shared__ float ts[32][33];
    int k0 = blockIdx.x * 32;
    int j0 = blockIdx.y * 32;
    int tx = threadIdx.x & 31, ty = threadIdx.x >> 5;
    #pragma unroll
    for (int r = 0; r < 4; r++) {
        int k = k0 + ty + r * 8;
        ts[ty + r * 8][tx] = W1[(size_t)k * DD + j0 + tx] * g_s1[k];
    }
    __syncthreads();
    #pragma unroll
    for (int r = 0; r < 4; r++) {
        int j = j0 + ty + r * 8;
        float x = ts[tx][ty + r * 8] * g_d[j];
        __nv_bfloat16 h, l; split_hl(x, h, l);
        g_BTh[(size_t)j * HH + k0 + tx] = h;
        g_BTl[(size_t)j * HH + k0 + tx] = l;
    }
}

// ---- K3b: t/v columns of E2 via fp32 matvec (side stream, overlaps k3) ----
// tcol[i] = sum_k W2[i][k]*t1[k];  vcol[i] = sum_k W2[i][k]*v1p[k]
__global__ void k3b_tv(const float* __restrict__ W2) {
    int row  = blockIdx.x * 8 + (threadIdx.x >> 5);
    int lane = threadIdx.x & 31;
    const float* w = W2 + (size_t)row * HH;
    float st = 0.f, sv = 0.f;
    for (int j = lane * 4; j < HH; j += 128) {
        float4 wv = *(const float4*)(w + j);
        float4 tt = *(const float4*)(g_t1 + j);
        float4 vv = *(const float4*)(g_v1p + j);
        st += wv.x * tt.x + wv.y * tt.y + wv.z * tt.z + wv.w * tt.w;
        sv += wv.x * vv.x + wv.y * vv.y + wv.z * vv.z + wv.w * vv.w;
    }
    #pragma unroll
    for (int o = 16; o; o >>= 1) {
        st += __shfl_xor_sync(0xffffffffu, st, o);
        sv += __shfl_xor_sync(0xffffffffu, sv, o);
    }
    if (lane == 0) { g_tcol[row] = st; g_vcol[row] = sv; }
}

// ================== K3: mma.sync bf16 GEMM, 128x128 tile, k-split 4 ==========
// CTA: 128 threads (4 warps, 2x2), warp tile 64x64. BK=32, 32 k-groups/CTA.
// Stage 32KB: Ah@0 Al@8K Bh@16K Bl@24K. 2-stage ring. Grid (8, 32, 4).
#define K3_STG 32768
#define K3_SMEM (2 * K3_STG)
#define NKG3 32

__global__ __launch_bounds__(128, 2) void k3_mma() {
    extern __shared__ __align__(1024) unsigned char sm[];
    const int tid  = threadIdx.x;
    const int lane = tid & 31;
    const int wid  = tid >> 5;
    const int warp_m = wid & 1;
    const int warp_n = wid >> 1;
    const int j0 = blockIdx.x * 128;
    const int i0 = blockIdx.y * 128;
    const int kbase = blockIdx.z * (HH / KSPL);
    const uint32_t sbase = smem_u32(sm);

    const int ra = (lane & 7) + (((lane >> 3) & 1) << 3);
    const int ha = lane >> 4;
    const int rb = (lane & 7) + ((lane >> 4) << 3);
    const int hb = (lane >> 3) & 1;
    uint32_t offA[4][2], offB[4][2];
    #pragma unroll
    for (int mf = 0; mf < 4; mf++)
        #pragma unroll
        for (int kk = 0; kk < 2; kk++) {
            int row = warp_m * 64 + mf * 16 + ra;
            int c   = kk * 2 + ha;
            offA[mf][kk] = row * 64 + ((c ^ ((row >> 1) & 3)) << 4);
        }
    #pragma unroll
    for (int nf4 = 0; nf4 < 4; nf4++)
        #pragma unroll
        for (int kk = 0; kk < 2; kk++) {
            int row = warp_n * 64 + nf4 * 16 + rb;
            int c   = kk * 2 + hb;
            offB[nf4][kk] = row * 64 + ((c ^ ((row >> 1) & 3)) << 4);
        }

    // fill one stage: 2048 cp16 total, 16 per thread
    auto fill = [&](int stage, int kg) {
        const uint32_t base = sbase + stage * K3_STG;
        const int kgo = kbase + kg * 32;
        #pragma unroll
        for (int s = 0; s < 4; s++) {
            int q = s * 128 + tid;          // 0..511
            int r = q >> 2, c = q & 3;
            uint32_t sw = r * 64 + ((c ^ ((r >> 1) & 3)) << 4);
            const size_t goA = (size_t)(i0 + r) * HH + kgo + c * 8;
            cp16(base + sw,         g_W2h + goA);
            cp16(base + 8192 + sw,  g_W2l + goA);
            const size_t goB = (size_t)(j0 + r) * HH + kgo + c * 8;
            cp16(base + 16384 + sw, g_BTh + goB);
            cp16(base + 24576 + sw, g_BTl + goB);
        }
        cp_commit();
    };

    float acc[4][8][4];
    #pragma unroll
    for (int mf = 0; mf < 4; mf++)
        #pragma unroll
        for (int nf = 0; nf < 8; nf++)
            #pragma unroll
            for (int q = 0; q < 4; q++) acc[mf][nf][q] = 0.f;

    fill(0, 0);

    for (int kg = 0; kg < NKG3; ++kg) {
        cp_wait<0>();
        __syncthreads();
        if (kg + 1 < NKG3) fill((kg + 1) & 1, kg + 1);
        const uint32_t base = sbase + (kg & 1) * K3_STG;
        #pragma unroll
        for (int kk = 0; kk < 2; kk++) {
            uint32_t a[4][4], bh[8][2], bl[8][2];
            #pragma unroll
            for (int mf = 0; mf < 4; mf++)
                LDSM4(a[mf][0], a[mf][1], a[mf][2], a[mf][3], base + offA[mf][kk]);
            #pragma unroll
            for (int nf4 = 0; nf4 < 4; nf4++) {
                uint32_t r0, r1, r2, r3;
                LDSM4(r0, r1, r2, r3, base + 16384 + offB[nf4][kk]);
                bh[nf4 * 2][0] = r0;     bh[nf4 * 2][1] = r1;
                bh[nf4 * 2 + 1][0] = r2; bh[nf4 * 2 + 1][1] = r3;
            }
            #pragma unroll
            for (int nf4 = 0; nf4 < 4; nf4++) {
                uint32_t r0, r1, r2, r3;
                LDSM4(r0, r1, r2, r3, base + 24576 + offB[nf4][kk]);
                bl[nf4 * 2][0] = r0;     bl[nf4 * 2][1] = r1;
                bl[nf4 * 2 + 1][0] = r2; bl[nf4 * 2 + 1][1] = r3;
            }
            #pragma unroll
            for (int mf = 0; mf < 4; mf++)
                #pragma unroll
                for (int nf = 0; nf < 8; nf++)
                    MMA16816(acc[mf][nf], a[mf], bh[nf]);
            #pragma unroll
            for (int mf = 0; mf < 4; mf++)
                #pragma unroll
                for (int nf = 0; nf < 8; nf++)
                    MMA16816(acc[mf][nf], a[mf], bl[nf]);
            #pragma unroll
            for (int mf = 0; mf < 4; mf++)
                LDSM4(a[mf][0], a[mf][1], a[mf][2], a[mf][3], base + 8192 + offA[mf][kk]);
            #pragma unroll
            for (int mf = 0; mf < 4; mf++)
                #pragma unroll
                for (int nf = 0; nf < 8; nf++)
                    MMA16816(acc[mf][nf], a[mf], bh[nf]);
        }
    }

    // epilogue -> partial buffer blockIdx.z
    float* outp = g_E2p + (size_t)blockIdx.z * HH * NE;
    const int er = lane >> 2;
    const int ec = (lane & 3) * 2;
    #pragma unroll
    for (int mf = 0; mf < 4; mf++) {
        #pragma unroll
        for (int nf = 0; nf < 8; nf++) {
            int row = i0 + warp_m * 64 + mf * 16 + er;
            int col = j0 + warp_n * 64 + nf * 8 + ec;
            *(float2*)(outp + (size_t)row * NE + col)       = make_float2(acc[mf][nf][0], acc[mf][nf][1]);
            *(float2*)(outp + (size_t)(row + 8) * NE + col) = make_float2(acc[mf][nf][2], acc[mf][nf][3]);
        }
    }
}

// ---- K4: sum partials, row-wise |.| reduce + ReLU params ----
__global__ void k4_relu2(const float* __restrict__ b2) {
    int row  = blockIdx.x * 8 + (threadIdx.x >> 5);
    int lane = threadIdx.x & 31;
    const float* e0 = g_E2p + (size_t)row * NE;
    const float* e1 = e0 + (size_t)HH * NE;
    const float* e2 = e1 + (size_t)HH * NE;
    const float* e3 = e2 + (size_t)HH * NE;
    float sr = 0.f;
    for (int j = lane * 4; j < NE; j += 128) {
        float4 a = *(const float4*)(e0 + j);
        float4 b = *(const float4*)(e1 + j);
        float4 c = *(const float4*)(e2 + j);
        float4 d = *(const float4*)(e3 + j);
        sr += fabsf(a.x + b.x + c.x + d.x) + fabsf(a.y + b.y + c.y + d.y)
            + fabsf(a.z + b.z + c.z + d.z) + fabsf(a.w + b.w + c.w + d.w);
    }
    #pragma unroll
    for (int o = 16; o; o >>= 1) sr += __shfl_xor_sync(0xffffffffu, sr, o);
    if (lane == 0) {
        sr += fabsf(g_tcol[row]);
        float v = g_vcol[row] + b2[row];
        float s, t, vn;
        relu_params(v, sr, s, t, vn);
        g_s2[row] = s; g_t2[row] = t; g_v2p[row] = vn;
    }
}

// ---- K5: layer-3 partial GEMM (16-way deterministic k-split) ----
__global__ void k5_e3(const float* __restrict__ W3) {
    __shared__ float w3s[OO][256];
    __shared__ float s2s[256];
    const int jt = blockIdx.x, ks = blockIdx.y;
    const int k0 = ks * 256;
    const int tid = threadIdx.x;

    for (int idx = tid; idx < OO * 256; idx += 128) {
        int i = idx >> 8, kk = idx & 255;
        w3s[i][kk] = W3[(size_t)i * HH + k0 + kk];
    }
    for (int kk = tid; kk < 256; kk += 128) s2s[kk] = g_s2[k0 + kk];
    __syncthreads();

    const int j = jt * 128 + tid;
    float acc[OO];
    #pragma unroll
    for (int i = 0; i < OO; i++) acc[i] = 0.f;

    if (j < 1024) {
        const float* e0 = g_E2p + (size_t)k0 * NE + j;
        const float* e1 = e0 + (size_t)HH * NE;
        const float* e2 = e1 + (size_t)HH * NE;
        const float* e3 = e2 + (size_t)HH * NE;
        for (int kk = 0; kk < 256; ++kk) {
            size_t o = (size_t)kk * NE;
            float bval = s2s[kk] * (e0[o] + e1[o] + e2[o] + e3[o]);
            #pragma unroll
            for (int i = 0; i < OO; i++) acc[i] += w3s[i][kk] * bval;
        }
    } else if (j == 1024) {
        for (int kk = 0; kk < 256; ++kk) {
            float bval = s2s[kk] * g_tcol[k0 + kk];
            #pragma unroll
            for (int i = 0; i < OO; i++) acc[i] += w3s[i][kk] * bval;
        }
    } else if (j == 1025) {
        for (int kk = 0; kk < 256; ++kk) {
            float bval = g_t2[k0 + kk];
            #pragma unroll
            for (int i = 0; i < OO; i++) acc[i] += w3s[i][kk] * bval;
        }
    } else if (j == 1026) {
        for (int kk = 0; kk < 256; ++kk) {
            float bval = g_v2p[k0 + kk];
            #pragma unroll
            for (int i = 0; i < OO; i++) acc[i] += w3s[i][kk] * bval;
        }
    }
    if (j < NC3) {
        #pragma unroll
        for (int i = 0; i < OO; i++)
            g_E3p[((size_t)ks * OO + i) * SE3 + j] = acc[i];
    }
}

// ---- K6 ----
__global__ void k6_final(const float* __restrict__ b3, float* __restrict__ out) {
    const int i = blockIdx.x;
    const int tid = threadIdx.x;
    __shared__ float red[256];
    __shared__ float vsh;
    float racc = 0.f;
    for (int j = tid; j < NC3; j += 256) {
        float s = 0.f;
        #pragma unroll
        for (int ks = 0; ks < KS3; ks++) s += g_E3p[((size_t)ks * OO + i) * SE3 + j];
        if (j < 1026) racc += fabsf(s);
        else          vsh = s + b3[i];
    }
    red[tid] = racc;
    __syncthreads();
    for (int o = 128; o; o >>= 1) {
        if (tid < o) red[tid] += red[tid + o];
        __syncthreads();
    }
    if (tid == 0) {
        float v = vsh, r = red[0];
        out[i]      = v + r;
        out[10 + i] = v - r;
    }
}

extern "C" void kernel_launch(void* const* d_in, const int* in_sizes, int n_in,
                              void* d_out, int out_size) {
    const float* inputs = (const float*)d_in[0];
    const float* W1     = (const float*)d_in[1];
    const float* b1     = (const float*)d_in[2];
    const float* W2     = (const float*)d_in[3];
    const float* b2     = (const float*)d_in[4];
    const float* W3     = (const float*)d_in[5];
    const float* b3     = (const float*)d_in[6];
    float* out = (float*)d_out;

    static cudaStream_t sA = nullptr, sB = nullptr;
    static cudaEvent_t evF = nullptr, evA = nullptr, evK = nullptr, evB = nullptr;
    if (!sA) {
        cudaStreamCreateWithFlags(&sA, cudaStreamNonBlocking);
        cudaStreamCreateWithFlags(&sB, cudaStreamNonBlocking);
        cudaEventCreateWithFlags(&evF, cudaEventDisableTiming);
        cudaEventCreateWithFlags(&evA, cudaEventDisableTiming);
        cudaEventCreateWithFlags(&evK, cudaEventDisableTiming);
        cudaEventCreateWithFlags(&evB, cudaEventDisableTiming);
        cudaFuncSetAttribute(k3_mma, cudaFuncAttributeMaxDynamicSharedMemorySize, K3_SMEM);
    }

    // fork: W2 conversion on side stream A (independent of everything else)
    cudaEventRecord(evF, 0);
    cudaStreamWaitEvent(sA, evF, 0);
    k2a_convW2<<<((size_t)HH * HH / 4) / 256, 256, 0, sA>>>(W2);
    cudaEventRecord(evA, sA);

    // main chain
    k0_init<<<1, DD>>>(inputs);
    k1_layer1<<<HH / 8, 256>>>(W1, b1);

    // fork: t/v matvec on side stream B (needs k1 only; overlaps k2b + k3)
    cudaEventRecord(evK, 0);
    cudaStreamWaitEvent(sB, evK, 0);
    k3b_tv<<<HH / 8, 256, 0, sB>>>(W2);
    cudaEventRecord(evB, sB);

    dim3 g2b(HH / 32, DD / 32);
    k2b_buildBT<<<g2b, 256>>>(W1);

    cudaStreamWaitEvent(0, evA, 0);       // k3 needs W2h/W2l
    dim3 g3(NE / 128, HH / 128, KSPL);    // 8 x 32 x 4 = 1024 CTAs
    k3_mma<<<g3, 128, K3_SMEM>>>();

    cudaStreamWaitEvent(0, evB, 0);       // k4 needs tcol/vcol
    k4_relu2<<<HH / 8, 256>>>(b2);
    dim3 g5(9, KS3);
    k5_e3<<<g5, 128>>>(W3);
    k6_final<<<OO, 256>>>(b3, out);
}

// round 8
// speedup vs baseline: 3.8983x; 1.2010x over previous
#include <cuda_runtime.h>
#include <cuda_fp16.h>
#include <cstdint>

// Zonotope propagation: D=1024 -> H=4096 -> H=4096 -> O=10
// Heavy op: E2 = W2 @ Baug via mma.sync fp16, 2-pass split:
//   A = Ah + Al (fp16 hi/lo), B ~ Bh (fp16 round) ; E2 = Ah*Bh + Al*Bh
// Dropped term A*Bl ~ 2^-12 relative -> final rel_err ~1.5e-4 (< 1e-3).
// R7: 2-pass fp16 (33% fewer MMAs than 3-pass bf16), 24KB stages,
//     k4 writes summed E2 so k5 reads 16.8MB not 67MB.

#define DD 1024
#define HH 4096
#define OO 10
#define NE 1024
#define NC3 1027
#define SE3 1056
#define KS3 16
#define KSPL 4

#define C_EPS   0.01f
#define C_MEAN  0.1307f
#define C_SIGMA 0.3081f

// ---- device scratch ----
__device__ float g_v0[DD];
__device__ float g_d[DD];
__device__ float g_s1[HH];
__device__ float g_t1[HH];
__device__ float g_v1p[HH];
__device__ __half g_W2h[(size_t)HH * HH];          // 33.5 MB
__device__ __half g_W2l[(size_t)HH * HH];          // 33.5 MB
__device__ __half g_BTh[(size_t)NE * HH];          // 8.4 MB (BaugT fp16, K-major)
__device__ float g_E2p[(size_t)KSPL * HH * NE];    // 67 MB partials
__device__ float g_E2s[(size_t)HH * NE];           // 16.8 MB summed
__device__ float g_tcol[HH];
__device__ float g_vcol[HH];
__device__ float g_s2[HH];
__device__ float g_t2[HH];
__device__ float g_v2p[HH];
__device__ float g_E3p[KS3 * OO * SE3];

// ================= PTX helpers =================
static __device__ __forceinline__ uint32_t smem_u32(const void* p) {
    uint32_t a;
    asm("{ .reg .u64 t; cvta.to.shared.u64 t, %1; cvt.u32.u64 %0, t; }" : "=r"(a) : "l"(p));
    return a;
}
static __device__ __forceinline__ void cp16(uint32_t dst, const void* src) {
    asm volatile("cp.async.cg.shared.global [%0], [%1], 16;" :: "r"(dst), "l"(src));
}
static __device__ __forceinline__ void cp_commit() {
    asm volatile("cp.async.commit_group;" ::: "memory");
}
template <int N> static __device__ __forceinline__ void cp_wait() {
    asm volatile("cp.async.wait_group %0;" :: "n"(N) : "memory");
}
#define LDSM4(r0, r1, r2, r3, addr) \
    asm volatile("ldmatrix.sync.aligned.m8n8.x4.shared.b16 {%0,%1,%2,%3}, [%4];" \
                 : "=r"(r0), "=r"(r1), "=r"(r2), "=r"(r3) : "r"(addr))
#define MMA16816F(c, a, b) \
    asm volatile("mma.sync.aligned.m16n8k16.row.col.f32.f16.f16.f32 " \
                 "{%0,%1,%2,%3}, {%4,%5,%6,%7}, {%8,%9}, {%0,%1,%2,%3};" \
                 : "+f"((c)[0]), "+f"((c)[1]), "+f"((c)[2]), "+f"((c)[3]) \
                 : "r"((a)[0]), "r"((a)[1]), "r"((a)[2]), "r"((a)[3]), \
                   "r"((b)[0]), "r"((b)[1]))

static __device__ __forceinline__ void relu_params(float v, float r,
                                                   float& s, float& t, float& vn) {
    float u = v + r;
    float l = v - r;
    if (u <= 0.f)       { s = 0.f; t = 0.f; vn = 0.f; }
    else if (l < 0.f)   { float slope = u / (u - l); float term = (1.f - slope) * u * 0.5f;
                          s = slope; t = term; vn = slope * v + term; }
    else                { s = 1.f; t = 0.f; vn = v; }
}
static __device__ __forceinline__ void split_hl16(float x, __half& h, __half& l) {
    h = __float2half_rn(x);
    l = __float2half_rn(x - __half2float(h));
}

// ---- K0 ----
__global__ void k0_init(const float* __restrict__ in) {
    int j = threadIdx.x;
    float x  = in[j];
    float up = fminf(x + C_EPS, 1.f);
    float lo = fmaxf(x - C_EPS, 0.f);
    float val = up + lo;
    g_v0[j] = (val - C_MEAN) / C_SIGMA;
    g_d[j]  = up / C_SIGMA;
}

// ---- K1 ----
__global__ void k1_layer1(const float* __restrict__ W1, const float* __restrict__ b1) {
    int row  = blockIdx.x * 8 + (threadIdx.x >> 5);
    int lane = threadIdx.x & 31;
    const float* w = W1 + (size_t)row * DD;
    float sv = 0.f, sr = 0.f;
    #pragma unroll
    for (int j = lane * 4; j < DD; j += 128) {
        float4 wv = *(const float4*)(w + j);
        float4 v  = *(const float4*)(g_v0 + j);
        float4 dd = *(const float4*)(g_d + j);
        sv += wv.x * v.x + wv.y * v.y + wv.z * v.z + wv.w * v.w;
        sr += fabsf(wv.x) * dd.x + fabsf(wv.y) * dd.y
            + fabsf(wv.z) * dd.z + fabsf(wv.w) * dd.w;
    }
    #pragma unroll
    for (int o = 16; o; o >>= 1) {
        sv += __shfl_xor_sync(0xffffffffu, sv, o);
        sr += __shfl_xor_sync(0xffffffffu, sr, o);
    }
    if (lane == 0) {
        float v = sv + b1[row];
        float s, t, vn;
        relu_params(v, sr, s, t, vn);
        g_s1[row] = s; g_t1[row] = t; g_v1p[row] = vn;
    }
}

// ---- K2a: split W2 into fp16 hi/lo (side stream) ----
__global__ void k2a_convW2(const float* __restrict__ W2) {
    size_t i4 = (size_t)blockIdx.x * blockDim.x + threadIdx.x;
    float4 x = *(const float4*)(W2 + i4 * 4);
    __half h0,h1,h2,h3,l0,l1,l2,l3;
    split_hl16(x.x,h0,l0); split_hl16(x.y,h1,l1); split_hl16(x.z,h2,l2); split_hl16(x.w,h3,l3);
    ushort4 hh = make_ushort4(__half_as_ushort(h0), __half_as_ushort(h1),
                              __half_as_ushort(h2), __half_as_ushort(h3));
    ushort4 ll = make_ushort4(__half_as_ushort(l0), __half_as_ushort(l1),
                              __half_as_ushort(l2), __half_as_ushort(l3));
    *(ushort4*)((unsigned short*)g_W2h + i4 * 4) = hh;
    *(ushort4*)((unsigned short*)g_W2l + i4 * 4) = ll;
}

// ---- K2b: BaugT rows 0..1023 in fp16 ----
__global__ void k2b_buildBT(const float* __restrict__ W1) {
    __shared__ float ts[32][33];
    int k0 = blockIdx.x * 32;
    int j0 = blockIdx.y * 32;
    int tx = threadIdx.x & 31, ty = threadIdx.x >> 5;
    #pragma unroll
    for (int r = 0; r < 4; r++) {
        int k = k0 + ty + r * 8;
        ts[ty + r * 8][tx] = W1[(size_t)k * DD + j0 + tx] * g_s1[k];
    }
    __syncthreads();
    #pragma unroll
    for (int r = 0; r < 4; r++) {
        int j = j0 + ty + r * 8;
        float x = ts[tx][ty + r * 8] * g_d[j];
        g_BTh[(size_t)j * HH + k0 + tx] = __float2half_rn(x);
    }
}

// ---- K3b: t/v columns of E2 via fp32 matvec (side stream) ----
__global__ void k3b_tv(const float* __restrict__ W2) {
    int row  = blockIdx.x * 8 + (threadIdx.x >> 5);
    int lane = threadIdx.x & 31;
    const float* w = W2 + (size_t)row * HH;
    float st = 0.f, sv = 0.f;
    for (int j = lane * 4; j < HH; j += 128) {
        float4 wv = *(const float4*)(w + j);
        float4 tt = *(const float4*)(g_t1 + j);
        float4 vv = *(const float4*)(g_v1p + j);
        st += wv.x * tt.x + wv.y * tt.y + wv.z * tt.z + wv.w * tt.w;
        sv += wv.x * vv.x + wv.y * vv.y + wv.z * vv.z + wv.w * vv.w;
    }
    #pragma unroll
    for (int o = 16; o; o >>= 1) {
        st += __shfl_xor_sync(0xffffffffu, st, o);
        sv += __shfl_xor_sync(0xffffffffu, sv, o);
    }
    if (lane == 0) { g_tcol[row] = st; g_vcol[row] = sv; }
}

// ================== K3: mma.sync fp16 GEMM, 2-pass, 128x128, k-split 4 ========
// Stage 24KB: Ah@0 Al@8K Bh@16K. 2-stage ring. Grid (8, 32, 4), 128 thr, occ 2.
#define K3_STG 24576
#define K3_SMEM (2 * K3_STG)
#define NKG3 32

__global__ __launch_bounds__(128, 2) void k3_mma() {
    extern __shared__ __align__(1024) unsigned char sm[];
    const int tid  = threadIdx.x;
    const int lane = tid & 31;
    const int wid  = tid >> 5;
    const int warp_m = wid & 1;
    const int warp_n = wid >> 1;
    const int j0 = blockIdx.x * 128;
    const int i0 = blockIdx.y * 128;
    const int kbase = blockIdx.z * (HH / KSPL);
    const uint32_t sbase = smem_u32(sm);

    const int ra = (lane & 7) + (((lane >> 3) & 1) << 3);
    const int ha = lane >> 4;
    const int rb = (lane & 7) + ((lane >> 4) << 3);
    const int hb = (lane >> 3) & 1;
    uint32_t offA[4][2], offB[4][2];
    #pragma unroll
    for (int mf = 0; mf < 4; mf++)
        #pragma unroll
        for (int kk = 0; kk < 2; kk++) {
            int row = warp_m * 64 + mf * 16 + ra;
            int c   = kk * 2 + ha;
            offA[mf][kk] = row * 64 + ((c ^ ((row >> 1) & 3)) << 4);
        }
    #pragma unroll
    for (int nf4 = 0; nf4 < 4; nf4++)
        #pragma unroll
        for (int kk = 0; kk < 2; kk++) {
            int row = warp_n * 64 + nf4 * 16 + rb;
            int c   = kk * 2 + hb;
            offB[nf4][kk] = row * 64 + ((c ^ ((row >> 1) & 3)) << 4);
        }

    // fill one stage: 1536 cp16 total, 12 per thread
    auto fill = [&](int stage, int kg) {
        const uint32_t base = sbase + stage * K3_STG;
        const int kgo = kbase + kg * 32;
        #pragma unroll
        for (int s = 0; s < 4; s++) {
            int q = s * 128 + tid;          // 0..511
            int r = q >> 2, c = q & 3;
            uint32_t sw = r * 64 + ((c ^ ((r >> 1) & 3)) << 4);
            const size_t goA = (size_t)(i0 + r) * HH + kgo + c * 8;
            cp16(base + sw,         g_W2h + goA);
            cp16(base + 8192 + sw,  g_W2l + goA);
            const size_t goB = (size_t)(j0 + r) * HH + kgo + c * 8;
            cp16(base + 16384 + sw, g_BTh + goB);
        }
        cp_commit();
    };

    float acc[4][8][4];
    #pragma unroll
    for (int mf = 0; mf < 4; mf++)
        #pragma unroll
        for (int nf = 0; nf < 8; nf++)
            #pragma unroll
            for (int q = 0; q < 4; q++) acc[mf][nf][q] = 0.f;

    fill(0, 0);

    for (int kg = 0; kg < NKG3; ++kg) {
        cp_wait<0>();
        __syncthreads();
        if (kg + 1 < NKG3) fill((kg + 1) & 1, kg + 1);
        const uint32_t base = sbase + (kg & 1) * K3_STG;
        #pragma unroll
        for (int kk = 0; kk < 2; kk++) {
            uint32_t a[4][4], bh[8][2];
            #pragma unroll
            for (int mf = 0; mf < 4; mf++)
                LDSM4(a[mf][0], a[mf][1], a[mf][2], a[mf][3], base + offA[mf][kk]);
            #pragma unroll
            for (int nf4 = 0; nf4 < 4; nf4++) {
                uint32_t r0, r1, r2, r3;
                LDSM4(r0, r1, r2, r3, base + 16384 + offB[nf4][kk]);
                bh[nf4 * 2][0] = r0;     bh[nf4 * 2][1] = r1;
                bh[nf4 * 2 + 1][0] = r2; bh[nf4 * 2 + 1][1] = r3;
            }
            // pass 0: Ah * Bh
            #pragma unroll
            for (int mf = 0; mf < 4; mf++)
                #pragma unroll
                for (int nf = 0; nf < 8; nf++)
                    MMA16816F(acc[mf][nf], a[mf], bh[nf]);
            // reload A regs with Al, pass 1: Al * Bh
            #pragma unroll
            for (int mf = 0; mf < 4; mf++)
                LDSM4(a[mf][0], a[mf][1], a[mf][2], a[mf][3], base + 8192 + offA[mf][kk]);
            #pragma unroll
            for (int mf = 0; mf < 4; mf++)
                #pragma unroll
                for (int nf = 0; nf < 8; nf++)
                    MMA16816F(acc[mf][nf], a[mf], bh[nf]);
        }
    }

    // epilogue -> partial buffer blockIdx.z
    float* outp = g_E2p + (size_t)blockIdx.z * HH * NE;
    const int er = lane >> 2;
    const int ec = (lane & 3) * 2;
    #pragma unroll
    for (int mf = 0; mf < 4; mf++) {
        #pragma unroll
        for (int nf = 0; nf < 8; nf++) {
            int row = i0 + warp_m * 64 + mf * 16 + er;
            int col = j0 + warp_n * 64 + nf * 8 + ec;
            *(float2*)(outp + (size_t)row * NE + col)       = make_float2(acc[mf][nf][0], acc[mf][nf][1]);
            *(float2*)(outp + (size_t)(row + 8) * NE + col) = make_float2(acc[mf][nf][2], acc[mf][nf][3]);
        }
    }
}

// ---- K4: sum partials -> g_E2s, row |.| reduce + ReLU params ----
__global__ void k4_relu2(const float* __restrict__ b2) {
    int row  = blockIdx.x * 8 + (threadIdx.x >> 5);
    int lane = threadIdx.x & 31;
    const float* e0 = g_E2p + (size_t)row * NE;
    const float* e1 = e0 + (size_t)HH * NE;
    const float* e2 = e1 + (size_t)HH * NE;
    const float* e3 = e2 + (size_t)HH * NE;
    float* es = g_E2s + (size_t)row * NE;
    float sr = 0.f;
    for (int j = lane * 4; j < NE; j += 128) {
        float4 a = *(const float4*)(e0 + j);
        float4 b = *(const float4*)(e1 + j);
        float4 c = *(const float4*)(e2 + j);
        float4 d = *(const float4*)(e3 + j);
        float4 s4 = make_float4(a.x + b.x + c.x + d.x, a.y + b.y + c.y + d.y,
                                a.z + b.z + c.z + d.z, a.w + b.w + c.w + d.w);
        *(float4*)(es + j) = s4;
        sr += fabsf(s4.x) + fabsf(s4.y) + fabsf(s4.z) + fabsf(s4.w);
    }
    #pragma unroll
    for (int o = 16; o; o >>= 1) sr += __shfl_xor_sync(0xffffffffu, sr, o);
    if (lane == 0) {
        sr += fabsf(g_tcol[row]);
        float v = g_vcol[row] + b2[row];
        float s, t, vn;
        relu_params(v, sr, s, t, vn);
        g_s2[row] = s; g_t2[row] = t; g_v2p[row] = vn;
    }
}

// ---- K5: layer-3 partial GEMM (16-way deterministic k-split) ----
__global__ void k5_e3(const float* __restrict__ W3) {
    __shared__ float w3s[OO][256];
    __shared__ float s2s[256];
    const int jt = blockIdx.x, ks = blockIdx.y;
    const int k0 = ks * 256;
    const int tid = threadIdx.x;

    for (int idx = tid; idx < OO * 256; idx += 128) {
        int i = idx >> 8, kk = idx & 255;
        w3s[i][kk] = W3[(size_t)i * HH + k0 + kk];
    }
    for (int kk = tid; kk < 256; kk += 128) s2s[kk] = g_s2[k0 + kk];
    __syncthreads();

    const int j = jt * 128 + tid;
    float acc[OO];
    #pragma unroll
    for (int i = 0; i < OO; i++) acc[i] = 0.f;

    if (j < 1024) {
        const float* e = g_E2s + (size_t)k0 * NE + j;
        for (int kk = 0; kk < 256; ++kk) {
            float bval = s2s[kk] * e[(size_t)kk * NE];
            #pragma unroll
            for (int i = 0; i < OO; i++) acc[i] += w3s[i][kk] * bval;
        }
    } else if (j == 1024) {
        for (int kk = 0; kk < 256; ++kk) {
            float bval = s2s[kk] * g_tcol[k0 + kk];
            #pragma unroll
            for (int i = 0; i < OO; i++) acc[i] += w3s[i][kk] * bval;
        }
    } else if (j == 1025) {
        for (int kk = 0; kk < 256; ++kk) {
            float bval = g_t2[k0 + kk];
            #pragma unroll
            for (int i = 0; i < OO; i++) acc[i] += w3s[i][kk] * bval;
        }
    } else if (j == 1026) {
        for (int kk = 0; kk < 256; ++kk) {
            float bval = g_v2p[k0 + kk];
            #pragma unroll
            for (int i = 0; i < OO; i++) acc[i] += w3s[i][kk] * bval;
        }
    }
    if (j < NC3) {
        #pragma unroll
        for (int i = 0; i < OO; i++)
            g_E3p[((size_t)ks * OO + i) * SE3 + j] = acc[i];
    }
}

// ---- K6 ----
__global__ void k6_final(const float* __restrict__ b3, float* __restrict__ out) {
    const int i = blockIdx.x;
    const int tid = threadIdx.x;
    __shared__ float red[256];
    __shared__ float vsh;
    float racc = 0.f;
    for (int j = tid; j < NC3; j += 256) {
        float s = 0.f;
        #pragma unroll
        for (int ks = 0; ks < KS3; ks++) s += g_E3p[((size_t)ks * OO + i) * SE3 + j];
        if (j < 1026) racc += fabsf(s);
        else          vsh = s + b3[i];
    }
    red[tid] = racc;
    __syncthreads();
    for (int o = 128; o; o >>= 1) {
        if (tid < o) red[tid] += red[tid + o];
        __syncthreads();
    }
    if (tid == 0) {
        float v = vsh, r = red[0];
        out[i]      = v + r;
        out[10 + i] = v - r;
    }
}

extern "C" void kernel_launch(void* const* d_in, const int* in_sizes, int n_in,
                              void* d_out, int out_size) {
    const float* inputs = (const float*)d_in[0];
    const float* W1     = (const float*)d_in[1];
    const float* b1     = (const float*)d_in[2];
    const float* W2     = (const float*)d_in[3];
    const float* b2     = (const float*)d_in[4];
    const float* W3     = (const float*)d_in[5];
    const float* b3     = (const float*)d_in[6];
    float* out = (float*)d_out;

    static cudaStream_t sA = nullptr, sB = nullptr;
    static cudaEvent_t evF = nullptr, evA = nullptr, evK = nullptr, evB = nullptr;
    if (!sA) {
        cudaStreamCreateWithFlags(&sA, cudaStreamNonBlocking);
        cudaStreamCreateWithFlags(&sB, cudaStreamNonBlocking);
        cudaEventCreateWithFlags(&evF, cudaEventDisableTiming);
        cudaEventCreateWithFlags(&evA, cudaEventDisableTiming);
        cudaEventCreateWithFlags(&evK, cudaEventDisableTiming);
        cudaEventCreateWithFlags(&evB, cudaEventDisableTiming);
        cudaFuncSetAttribute(k3_mma, cudaFuncAttributeMaxDynamicSharedMemorySize, K3_SMEM);
    }

    // fork: W2 fp16 split on side stream A
    cudaEventRecord(evF, 0);
    cudaStreamWaitEvent(sA, evF, 0);
    k2a_convW2<<<((size_t)HH * HH / 4) / 256, 256, 0, sA>>>(W2);
    cudaEventRecord(evA, sA);

    // main chain
    k0_init<<<1, DD>>>(inputs);
    k1_layer1<<<HH / 8, 256>>>(W1, b1);

    // fork: t/v matvec on side stream B (needs k1 only)
    cudaEventRecord(evK, 0);
    cudaStreamWaitEvent(sB, evK, 0);
    k3b_tv<<<HH / 8, 256, 0, sB>>>(W2);
    cudaEventRecord(evB, sB);

    dim3 g2b(HH / 32, DD / 32);
    k2b_buildBT<<<g2b, 256>>>(W1);

    cudaStreamWaitEvent(0, evA, 0);
    dim3 g3(NE / 128, HH / 128, KSPL);
    k3_mma<<<g3, 128, K3_SMEM>>>();

    cudaStreamWaitEvent(0, evB, 0);
    k4_relu2<<<HH / 8, 256>>>(b2);
    dim3 g5(9, KS3);
    k5_e3<<<g5, 128>>>(W3);
    k6_final<<<OO, 256>>>(b3, out);
}

// round 9
// speedup vs baseline: 5.4750x; 1.4045x over previous
#include <cuda_runtime.h>
#include <cuda_fp16.h>
#include <cstdint>

// Zonotope propagation: D=1024 -> H=4096 -> H=4096 -> O=10
// Heavy op: E2 = W2 @ Baug via SINGLE-PASS fp16 mma.sync (fp32 accumulate).
// Calibration (R7): dropped 2^-12-scale terms attenuate ~60x through the
// |.|-sum bound structure -> measured 3.9e-6 with one dropped term; single
// pass drops two such terms -> predicted ~8e-6, >100x under the 1e-3 bar.
// R8: 1-pass fp16 (17.2 GMAC), 16KB stages, 3-stage cp.async ring.

#define DD 1024
#define HH 4096
#define OO 10
#define NE 1024
#define NC3 1027
#define SE3 1056
#define KS3 16
#define KSPL 4

#define C_EPS   0.01f
#define C_MEAN  0.1307f
#define C_SIGMA 0.3081f

// ---- device scratch ----
__device__ float g_v0[DD];
__device__ float g_d[DD];
__device__ float g_s1[HH];
__device__ float g_t1[HH];
__device__ float g_v1p[HH];
__device__ __half g_W2h[(size_t)HH * HH];          // 33.5 MB
__device__ __half g_BTh[(size_t)NE * HH];          // 8.4 MB (BaugT fp16, K-major)
__device__ float g_E2p[(size_t)KSPL * HH * NE];    // 67 MB partials
__device__ float g_E2s[(size_t)HH * NE];           // 16.8 MB summed
__device__ float g_tcol[HH];
__device__ float g_vcol[HH];
__device__ float g_s2[HH];
__device__ float g_t2[HH];
__device__ float g_v2p[HH];
__device__ float g_E3p[KS3 * OO * SE3];

// ================= PTX helpers =================
static __device__ __forceinline__ uint32_t smem_u32(const void* p) {
    uint32_t a;
    asm("{ .reg .u64 t; cvta.to.shared.u64 t, %1; cvt.u32.u64 %0, t; }" : "=r"(a) : "l"(p));
    return a;
}
static __device__ __forceinline__ void cp16(uint32_t dst, const void* src) {
    asm volatile("cp.async.cg.shared.global [%0], [%1], 16;" :: "r"(dst), "l"(src));
}
static __device__ __forceinline__ void cp_commit() {
    asm volatile("cp.async.commit_group;" ::: "memory");
}
template <int N> static __device__ __forceinline__ void cp_wait() {
    asm volatile("cp.async.wait_group %0;" :: "n"(N) : "memory");
}
#define LDSM4(r0, r1, r2, r3, addr) \
    asm volatile("ldmatrix.sync.aligned.m8n8.x4.shared.b16 {%0,%1,%2,%3}, [%4];" \
                 : "=r"(r0), "=r"(r1), "=r"(r2), "=r"(r3) : "r"(addr))
#define MMA16816F(c, a, b) \
    asm volatile("mma.sync.aligned.m16n8k16.row.col.f32.f16.f16.f32 " \
                 "{%0,%1,%2,%3}, {%4,%5,%6,%7}, {%8,%9}, {%0,%1,%2,%3};" \
                 : "+f"((c)[0]), "+f"((c)[1]), "+f"((c)[2]), "+f"((c)[3]) \
                 : "r"((a)[0]), "r"((a)[1]), "r"((a)[2]), "r"((a)[3]), \
                   "r"((b)[0]), "r"((b)[1]))

static __device__ __forceinline__ void relu_params(float v, float r,
                                                   float& s, float& t, float& vn) {
    float u = v + r;
    float l = v - r;
    if (u <= 0.f)       { s = 0.f; t = 0.f; vn = 0.f; }
    else if (l < 0.f)   { float slope = u / (u - l); float term = (1.f - slope) * u * 0.5f;
                          s = slope; t = term; vn = slope * v + term; }
    else                { s = 1.f; t = 0.f; vn = v; }
}

// ---- K0 ----
__global__ void k0_init(const float* __restrict__ in) {
    int j = threadIdx.x;
    float x  = in[j];
    float up = fminf(x + C_EPS, 1.f);
    float lo = fmaxf(x - C_EPS, 0.f);
    float val = up + lo;
    g_v0[j] = (val - C_MEAN) / C_SIGMA;
    g_d[j]  = up / C_SIGMA;
}

// ---- K1 ----
__global__ void k1_layer1(const float* __restrict__ W1, const float* __restrict__ b1) {
    int row  = blockIdx.x * 8 + (threadIdx.x >> 5);
    int lane = threadIdx.x & 31;
    const float* w = W1 + (size_t)row * DD;
    float sv = 0.f, sr = 0.f;
    #pragma unroll
    for (int j = lane * 4; j < DD; j += 128) {
        float4 wv = *(const float4*)(w + j);
        float4 v  = *(const float4*)(g_v0 + j);
        float4 dd = *(const float4*)(g_d + j);
        sv += wv.x * v.x + wv.y * v.y + wv.z * v.z + wv.w * v.w;
        sr += fabsf(wv.x) * dd.x + fabsf(wv.y) * dd.y
            + fabsf(wv.z) * dd.z + fabsf(wv.w) * dd.w;
    }
    #pragma unroll
    for (int o = 16; o; o >>= 1) {
        sv += __shfl_xor_sync(0xffffffffu, sv, o);
        sr += __shfl_xor_sync(0xffffffffu, sr, o);
    }
    if (lane == 0) {
        float v = sv + b1[row];
        float s, t, vn;
        relu_params(v, sr, s, t, vn);
        g_s1[row] = s; g_t1[row] = t; g_v1p[row] = vn;
    }
}

// ---- K2a: W2 -> fp16 (side stream) ----
__global__ void k2a_convW2(const float* __restrict__ W2) {
    size_t i4 = (size_t)blockIdx.x * blockDim.x + threadIdx.x;
    float4 x = *(const float4*)(W2 + i4 * 4);
    ushort4 hh = make_ushort4(__half_as_ushort(__float2half_rn(x.x)),
                              __half_as_ushort(__float2half_rn(x.y)),
                              __half_as_ushort(__float2half_rn(x.z)),
                              __half_as_ushort(__float2half_rn(x.w)));
    *(ushort4*)((unsigned short*)g_W2h + i4 * 4) = hh;
}

// ---- K2b: BaugT rows 0..1023 in fp16 ----
__global__ void k2b_buildBT(const float* __restrict__ W1) {
    __shared__ float ts[32][33];
    int k0 = blockIdx.x * 32;
    int j0 = blockIdx.y * 32;
    int tx = threadIdx.x & 31, ty = threadIdx.x >> 5;
    #pragma unroll
    for (int r = 0; r < 4; r++) {
        int k = k0 + ty + r * 8;
        ts[ty + r * 8][tx] = W1[(size_t)k * DD + j0 + tx] * g_s1[k];
    }
    __syncthreads();
    #pragma unroll
    for (int r = 0; r < 4; r++) {
        int j = j0 + ty + r * 8;
        float x = ts[tx][ty + r * 8] * g_d[j];
        g_BTh[(size_t)j * HH + k0 + tx] = __float2half_rn(x);
    }
}

// ---- K3b: t/v columns of E2 via fp32 matvec (side stream) ----
__global__ void k3b_tv(const float* __restrict__ W2) {
    int row  = blockIdx.x * 8 + (threadIdx.x >> 5);
    int lane = threadIdx.x & 31;
    const float* w = W2 + (size_t)row * HH;
    float st = 0.f, sv = 0.f;
    for (int j = lane * 4; j < HH; j += 128) {
        float4 wv = *(const float4*)(w + j);
        float4 tt = *(const float4*)(g_t1 + j);
        float4 vv = *(const float4*)(g_v1p + j);
        st += wv.x * tt.x + wv.y * tt.y + wv.z * tt.z + wv.w * tt.w;
        sv += wv.x * vv.x + wv.y * vv.y + wv.z * vv.z + wv.w * vv.w;
    }
    #pragma unroll
    for (int o = 16; o; o >>= 1) {
        st += __shfl_xor_sync(0xffffffffu, st, o);
        sv += __shfl_xor_sync(0xffffffffu, sv, o);
    }
    if (lane == 0) { g_tcol[row] = st; g_vcol[row] = sv; }
}

// ================== K3: single-pass fp16 GEMM, 128x128, k-split 4 ============
// Stage 16KB: Ah@0 Bh@8K. 3-stage ring. Grid (8, 32, 4), 128 thr, occ 2.
#define K3_STG 16384
#define K3_SMEM (3 * K3_STG)
#define NKG3 32

__global__ __launch_bounds__(128, 2) void k3_mma() {
    extern __shared__ __align__(1024) unsigned char sm[];
    const int tid  = threadIdx.x;
    const int lane = tid & 31;
    const int wid  = tid >> 5;
    const int warp_m = wid & 1;
    const int warp_n = wid >> 1;
    const int j0 = blockIdx.x * 128;
    const int i0 = blockIdx.y * 128;
    const int kbase = blockIdx.z * (HH / KSPL);
    const uint32_t sbase = smem_u32(sm);

    const int ra = (lane & 7) + (((lane >> 3) & 1) << 3);
    const int ha = lane >> 4;
    const int rb = (lane & 7) + ((lane >> 4) << 3);
    const int hb = (lane >> 3) & 1;
    uint32_t offA[4][2], offB[4][2];
    #pragma unroll
    for (int mf = 0; mf < 4; mf++)
        #pragma unroll
        for (int kk = 0; kk < 2; kk++) {
            int row = warp_m * 64 + mf * 16 + ra;
            int c   = kk * 2 + ha;
            offA[mf][kk] = row * 64 + ((c ^ ((row >> 1) & 3)) << 4);
        }
    #pragma unroll
    for (int nf4 = 0; nf4 < 4; nf4++)
        #pragma unroll
        for (int kk = 0; kk < 2; kk++) {
            int row = warp_n * 64 + nf4 * 16 + rb;
            int c   = kk * 2 + hb;
            offB[nf4][kk] = 8192 + row * 64 + ((c ^ ((row >> 1) & 3)) << 4);
        }

    // fill one stage: 1024 cp16 (512 A + 512 B), 8 per thread
    auto fill = [&](int stage, int kg) {
        const uint32_t base = sbase + stage * K3_STG;
        const int kgo = kbase + kg * 32;
        #pragma unroll
        for (int s = 0; s < 4; s++) {
            int q = s * 128 + tid;          // 0..511
            int r = q >> 2, c = q & 3;
            uint32_t sw = r * 64 + ((c ^ ((r >> 1) & 3)) << 4);
            cp16(base + sw,        g_W2h + (size_t)(i0 + r) * HH + kgo + c * 8);
            cp16(base + 8192 + sw, g_BTh + (size_t)(j0 + r) * HH + kgo + c * 8);
        }
        cp_commit();
    };

    float acc[4][8][4];
    #pragma unroll
    for (int mf = 0; mf < 4; mf++)
        #pragma unroll
        for (int nf = 0; nf < 8; nf++)
            #pragma unroll
            for (int q = 0; q < 4; q++) acc[mf][nf][q] = 0.f;

    fill(0, 0);
    fill(1, 1);

    for (int kg = 0; kg < NKG3; ++kg) {
        cp_wait<1>();
        __syncthreads();
        if (kg + 2 < NKG3) fill((kg + 2) % 3, kg + 2);
        const uint32_t base = sbase + (kg % 3) * K3_STG;
        #pragma unroll
        for (int kk = 0; kk < 2; kk++) {
            uint32_t a[4][4], bh[8][2];
            #pragma unroll
            for (int mf = 0; mf < 4; mf++)
                LDSM4(a[mf][0], a[mf][1], a[mf][2], a[mf][3], base + offA[mf][kk]);
            #pragma unroll
            for (int nf4 = 0; nf4 < 4; nf4++) {
                uint32_t r0, r1, r2, r3;
                LDSM4(r0, r1, r2, r3, base + offB[nf4][kk]);
                bh[nf4 * 2][0] = r0;     bh[nf4 * 2][1] = r1;
                bh[nf4 * 2 + 1][0] = r2; bh[nf4 * 2 + 1][1] = r3;
            }
            #pragma unroll
            for (int mf = 0; mf < 4; mf++)
                #pragma unroll
                for (int nf = 0; nf < 8; nf++)
                    MMA16816F(acc[mf][nf], a[mf], bh[nf]);
        }
    }

    // epilogue -> partial buffer blockIdx.z
    float* outp = g_E2p + (size_t)blockIdx.z * HH * NE;
    const int er = lane >> 2;
    const int ec = (lane & 3) * 2;
    #pragma unroll
    for (int mf = 0; mf < 4; mf++) {
        #pragma unroll
        for (int nf = 0; nf < 8; nf++) {
            int row = i0 + warp_m * 64 + mf * 16 + er;
            int col = j0 + warp_n * 64 + nf * 8 + ec;
            *(float2*)(outp + (size_t)row * NE + col)       = make_float2(acc[mf][nf][0], acc[mf][nf][1]);
            *(float2*)(outp + (size_t)(row + 8) * NE + col) = make_float2(acc[mf][nf][2], acc[mf][nf][3]);
        }
    }
}

// ---- K4: sum partials -> g_E2s, row |.| reduce + ReLU params ----
__global__ void k4_relu2(const float* __restrict__ b2) {
    int row  = blockIdx.x * 8 + (threadIdx.x >> 5);
    int lane = threadIdx.x & 31;
    const float* e0 = g_E2p + (size_t)row * NE;
    const float* e1 = e0 + (size_t)HH * NE;
    const float* e2 = e1 + (size_t)HH * NE;
    const float* e3 = e2 + (size_t)HH * NE;
    float* es = g_E2s + (size_t)row * NE;
    float sr = 0.f;
    for (int j = lane * 4; j < NE; j += 128) {
        float4 a = *(const float4*)(e0 + j);
        float4 b = *(const float4*)(e1 + j);
        float4 c = *(const float4*)(e2 + j);
        float4 d = *(const float4*)(e3 + j);
        float4 s4 = make_float4(a.x + b.x + c.x + d.x, a.y + b.y + c.y + d.y,
                                a.z + b.z + c.z + d.z, a.w + b.w + c.w + d.w);
        *(float4*)(es + j) = s4;
        sr += fabsf(s4.x) + fabsf(s4.y) + fabsf(s4.z) + fabsf(s4.w);
    }
    #pragma unroll
    for (int o = 16; o; o >>= 1) sr += __shfl_xor_sync(0xffffffffu, sr, o);
    if (lane == 0) {
        sr += fabsf(g_tcol[row]);
        float v = g_vcol[row] + b2[row];
        float s, t, vn;
        relu_params(v, sr, s, t, vn);
        g_s2[row] = s; g_t2[row] = t; g_v2p[row] = vn;
    }
}

// ---- K5: layer-3 partial GEMM (16-way deterministic k-split) ----
__global__ void k5_e3(const float* __restrict__ W3) {
    __shared__ float w3s[OO][256];
    __shared__ float s2s[256];
    const int jt = blockIdx.x, ks = blockIdx.y;
    const int k0 = ks * 256;
    const int tid = threadIdx.x;

    for (int idx = tid; idx < OO * 256; idx += 128) {
        int i = idx >> 8, kk = idx & 255;
        w3s[i][kk] = W3[(size_t)i * HH + k0 + kk];
    }
    for (int kk = tid; kk < 256; kk += 128) s2s[kk] = g_s2[k0 + kk];
    __syncthreads();

    const int j = jt * 128 + tid;
    float acc[OO];
    #pragma unroll
    for (int i = 0; i < OO; i++) acc[i] = 0.f;

    if (j < 1024) {
        const float* e = g_E2s + (size_t)k0 * NE + j;
        for (int kk = 0; kk < 256; ++kk) {
            float bval = s2s[kk] * e[(size_t)kk * NE];
            #pragma unroll
            for (int i = 0; i < OO; i++) acc[i] += w3s[i][kk] * bval;
        }
    } else if (j == 1024) {
        for (int kk = 0; kk < 256; ++kk) {
            float bval = s2s[kk] * g_tcol[k0 + kk];
            #pragma unroll
            for (int i = 0; i < OO; i++) acc[i] += w3s[i][kk] * bval;
        }
    } else if (j == 1025) {
        for (int kk = 0; kk < 256; ++kk) {
            float bval = g_t2[k0 + kk];
            #pragma unroll
            for (int i = 0; i < OO; i++) acc[i] += w3s[i][kk] * bval;
        }
    } else if (j == 1026) {
        for (int kk = 0; kk < 256; ++kk) {
            float bval = g_v2p[k0 + kk];
            #pragma unroll
            for (int i = 0; i < OO; i++) acc[i] += w3s[i][kk] * bval;
        }
    }
    if (j < NC3) {
        #pragma unroll
        for (int i = 0; i < OO; i++)
            g_E3p[((size_t)ks * OO + i) * SE3 + j] = acc[i];
    }
}

// ---- K6 ----
__global__ void k6_final(const float* __restrict__ b3, float* __restrict__ out) {
    const int i = blockIdx.x;
    const int tid = threadIdx.x;
    __shared__ float red[256];
    __shared__ float vsh;
    float racc = 0.f;
    for (int j = tid; j < NC3; j += 256) {
        float s = 0.f;
        #pragma unroll
        for (int ks = 0; ks < KS3; ks++) s += g_E3p[((size_t)ks * OO + i) * SE3 + j];
        if (j < 1026) racc += fabsf(s);
        else          vsh = s + b3[i];
    }
    red[tid] = racc;
    __syncthreads();
    for (int o = 128; o; o >>= 1) {
        if (tid < o) red[tid] += red[tid + o];
        __syncthreads();
    }
    if (tid == 0) {
        float v = vsh, r = red[0];
        out[i]      = v + r;
        out[10 + i] = v - r;
    }
}

extern "C" void kernel_launch(void* const* d_in, const int* in_sizes, int n_in,
                              void* d_out, int out_size) {
    const float* inputs = (const float*)d_in[0];
    const float* W1     = (const float*)d_in[1];
    const float* b1     = (const float*)d_in[2];
    const float* W2     = (const float*)d_in[3];
    const float* b2     = (const float*)d_in[4];
    const float* W3     = (const float*)d_in[5];
    const float* b3     = (const float*)d_in[6];
    float* out = (float*)d_out;

    static cudaStream_t sA = nullptr, sB = nullptr;
    static cudaEvent_t evF = nullptr, evA = nullptr, evK = nullptr, evB = nullptr;
    if (!sA) {
        cudaStreamCreateWithFlags(&sA, cudaStreamNonBlocking);
        cudaStreamCreateWithFlags(&sB, cudaStreamNonBlocking);
        cudaEventCreateWithFlags(&evF, cudaEventDisableTiming);
        cudaEventCreateWithFlags(&evA, cudaEventDisableTiming);
        cudaEventCreateWithFlags(&evK, cudaEventDisableTiming);
        cudaEventCreateWithFlags(&evB, cudaEventDisableTiming);
        cudaFuncSetAttribute(k3_mma, cudaFuncAttributeMaxDynamicSharedMemorySize, K3_SMEM);
    }

    // fork: W2 fp16 convert on side stream A
    cudaEventRecord(evF, 0);
    cudaStreamWaitEvent(sA, evF, 0);
    k2a_convW2<<<((size_t)HH * HH / 4) / 256, 256, 0, sA>>>(W2);
    cudaEventRecord(evA, sA);

    // main chain
    k0_init<<<1, DD>>>(inputs);
    k1_layer1<<<HH / 8, 256>>>(W1, b1);

    // fork: t/v matvec on side stream B (needs k1 only)
    cudaEventRecord(evK, 0);
    cudaStreamWaitEvent(sB, evK, 0);
    k3b_tv<<<HH / 8, 256, 0, sB>>>(W2);
    cudaEventRecord(evB, sB);

    dim3 g2b(HH / 32, DD / 32);
    k2b_buildBT<<<g2b, 256>>>(W1);

    cudaStreamWaitEvent(0, evA, 0);
    dim3 g3(NE / 128, HH / 128, KSPL);
    k3_mma<<<g3, 128, K3_SMEM>>>();

    cudaStreamWaitEvent(0, evB, 0);
    k4_relu2<<<HH / 8, 256>>>(b2);
    dim3 g5(9, KS3);
    k5_e3<<<g5, 128>>>(W3);
    k6_final<<<OO, 256>>>(b3, out);
}

// round 10
// speedup vs baseline: 6.0213x; 1.0998x over previous
#include <cuda_runtime.h>
#include <cuda_fp16.h>
#include <cstdint>

// Zonotope propagation: D=1024 -> H=4096 -> H=4096 -> O=10
// E2 = W2 @ Baug via single-pass fp16 mma.sync (fp32 acc), rel_err ~6e-6.
// R9: no k-split (256 CTAs = 1 wave @ occ 2), E2 written directly,
//     row-|.| sums fused into k3 epilogue -> k4 becomes trivial.

#define DD 1024
#define HH 4096
#define OO 10
#define NE 1024
#define NC3 1027
#define SE3 1056
#define KS3 16
#define NJT 8            // 8 column tiles of 128

#define C_EPS   0.01f
#define C_MEAN  0.1307f
#define C_SIGMA 0.3081f

// ---- device scratch ----
__device__ float g_v0[DD];
__device__ float g_d[DD];
__device__ float g_s1[HH];
__device__ float g_t1[HH];
__device__ float g_v1p[HH];
__device__ __half g_W2h[(size_t)HH * HH];      // 33.5 MB
__device__ __half g_BTh[(size_t)NE * HH];      // 8.4 MB (BaugT fp16, K-major)
__device__ float g_E2s[(size_t)HH * NE];       // 16.8 MB
__device__ float g_rpart[NJT][HH];             // per-jtile row |.| partial sums
__device__ float g_tcol[HH];
__device__ float g_vcol[HH];
__device__ float g_s2[HH];
__device__ float g_t2[HH];
__device__ float g_v2p[HH];
__device__ float g_E3p[KS3 * OO * SE3];

// ================= PTX helpers =================
static __device__ __forceinline__ uint32_t smem_u32(const void* p) {
    uint32_t a;
    asm("{ .reg .u64 t; cvta.to.shared.u64 t, %1; cvt.u32.u64 %0, t; }" : "=r"(a) : "l"(p));
    return a;
}
static __device__ __forceinline__ void cp16(uint32_t dst, const void* src) {
    asm volatile("cp.async.cg.shared.global [%0], [%1], 16;" :: "r"(dst), "l"(src));
}
static __device__ __forceinline__ void cp_commit() {
    asm volatile("cp.async.commit_group;" ::: "memory");
}
template <int N> static __device__ __forceinline__ void cp_wait() {
    asm volatile("cp.async.wait_group %0;" :: "n"(N) : "memory");
}
#define LDSM4(r0, r1, r2, r3, addr) \
    asm volatile("ldmatrix.sync.aligned.m8n8.x4.shared.b16 {%0,%1,%2,%3}, [%4];" \
                 : "=r"(r0), "=r"(r1), "=r"(r2), "=r"(r3) : "r"(addr))
#define MMA16816F(c, a, b) \
    asm volatile("mma.sync.aligned.m16n8k16.row.col.f32.f16.f16.f32 " \
                 "{%0,%1,%2,%3}, {%4,%5,%6,%7}, {%8,%9}, {%0,%1,%2,%3};" \
                 : "+f"((c)[0]), "+f"((c)[1]), "+f"((c)[2]), "+f"((c)[3]) \
                 : "r"((a)[0]), "r"((a)[1]), "r"((a)[2]), "r"((a)[3]), \
                   "r"((b)[0]), "r"((b)[1]))

static __device__ __forceinline__ void relu_params(float v, float r,
                                                   float& s, float& t, float& vn) {
    float u = v + r;
    float l = v - r;
    if (u <= 0.f)       { s = 0.f; t = 0.f; vn = 0.f; }
    else if (l < 0.f)   { float slope = u / (u - l); float term = (1.f - slope) * u * 0.5f;
                          s = slope; t = term; vn = slope * v + term; }
    else                { s = 1.f; t = 0.f; vn = v; }
}

// ---- K0 ----
__global__ void k0_init(const float* __restrict__ in) {
    int j = threadIdx.x;
    float x  = in[j];
    float up = fminf(x + C_EPS, 1.f);
    float lo = fmaxf(x - C_EPS, 0.f);
    float val = up + lo;
    g_v0[j] = (val - C_MEAN) / C_SIGMA;
    g_d[j]  = up / C_SIGMA;
}

// ---- K1 ----
__global__ void k1_layer1(const float* __restrict__ W1, const float* __restrict__ b1) {
    int row  = blockIdx.x * 8 + (threadIdx.x >> 5);
    int lane = threadIdx.x & 31;
    const float* w = W1 + (size_t)row * DD;
    float sv = 0.f, sr = 0.f;
    #pragma unroll
    for (int j = lane * 4; j < DD; j += 128) {
        float4 wv = *(const float4*)(w + j);
        float4 v  = *(const float4*)(g_v0 + j);
        float4 dd = *(const float4*)(g_d + j);
        sv += wv.x * v.x + wv.y * v.y + wv.z * v.z + wv.w * v.w;
        sr += fabsf(wv.x) * dd.x + fabsf(wv.y) * dd.y
            + fabsf(wv.z) * dd.z + fabsf(wv.w) * dd.w;
    }
    #pragma unroll
    for (int o = 16; o; o >>= 1) {
        sv += __shfl_xor_sync(0xffffffffu, sv, o);
        sr += __shfl_xor_sync(0xffffffffu, sr, o);
    }
    if (lane == 0) {
        float v = sv + b1[row];
        float s, t, vn;
        relu_params(v, sr, s, t, vn);
        g_s1[row] = s; g_t1[row] = t; g_v1p[row] = vn;
    }
}

// ---- K2a: W2 -> fp16 (side stream) ----
__global__ void k2a_convW2(const float* __restrict__ W2) {
    size_t i4 = (size_t)blockIdx.x * blockDim.x + threadIdx.x;
    float4 x = *(const float4*)(W2 + i4 * 4);
    ushort4 hh = make_ushort4(__half_as_ushort(__float2half_rn(x.x)),
                              __half_as_ushort(__float2half_rn(x.y)),
                              __half_as_ushort(__float2half_rn(x.z)),
                              __half_as_ushort(__float2half_rn(x.w)));
    *(ushort4*)((unsigned short*)g_W2h + i4 * 4) = hh;
}

// ---- K2b: BaugT rows 0..1023 in fp16 ----
__global__ void k2b_buildBT(const float* __restrict__ W1) {
    __shared__ float ts[32][33];
    int k0 = blockIdx.x * 32;
    int j0 = blockIdx.y * 32;
    int tx = threadIdx.x & 31, ty = threadIdx.x >> 5;
    #pragma unroll
    for (int r = 0; r < 4; r++) {
        int k = k0 + ty + r * 8;
        ts[ty + r * 8][tx] = W1[(size_t)k * DD + j0 + tx] * g_s1[k];
    }
    __syncthreads();
    #pragma unroll
    for (int r = 0; r < 4; r++) {
        int j = j0 + ty + r * 8;
        float x = ts[tx][ty + r * 8] * g_d[j];
        g_BTh[(size_t)j * HH + k0 + tx] = __float2half_rn(x);
    }
}

// ---- K3b: t/v columns of E2 via fp32 matvec (side stream) ----
__global__ void k3b_tv(const float* __restrict__ W2) {
    int row  = blockIdx.x * 8 + (threadIdx.x >> 5);
    int lane = threadIdx.x & 31;
    const float* w = W2 + (size_t)row * HH;
    float st = 0.f, sv = 0.f;
    for (int j = lane * 4; j < HH; j += 128) {
        float4 wv = *(const float4*)(w + j);
        float4 tt = *(const float4*)(g_t1 + j);
        float4 vv = *(const float4*)(g_v1p + j);
        st += wv.x * tt.x + wv.y * tt.y + wv.z * tt.z + wv.w * tt.w;
        sv += wv.x * vv.x + wv.y * vv.y + wv.z * vv.z + wv.w * vv.w;
    }
    #pragma unroll
    for (int o = 16; o; o >>= 1) {
        st += __shfl_xor_sync(0xffffffffu, st, o);
        sv += __shfl_xor_sync(0xffffffffu, sv, o);
    }
    if (lane == 0) { g_tcol[row] = st; g_vcol[row] = sv; }
}

// ================== K3: single-pass fp16 GEMM, 128x128, full-K, fused rowsum ==
// Stage 16KB: Ah@0 Bh@8K. 3-stage ring. Grid (8, 32), 128 thr, occ 2.
#define K3_STG 16384
#define K3_SMEM (3 * K3_STG)
#define NKG3 128

__global__ __launch_bounds__(128, 2) void k3_mma() {
    extern __shared__ __align__(1024) unsigned char sm[];
    __shared__ float rs[2][128];
    const int tid  = threadIdx.x;
    const int lane = tid & 31;
    const int wid  = tid >> 5;
    const int warp_m = wid & 1;
    const int warp_n = wid >> 1;
    const int j0 = blockIdx.x * 128;
    const int i0 = blockIdx.y * 128;
    const uint32_t sbase = smem_u32(sm);

    const int ra = (lane & 7) + (((lane >> 3) & 1) << 3);
    const int ha = lane >> 4;
    const int rb = (lane & 7) + ((lane >> 4) << 3);
    const int hb = (lane >> 3) & 1;
    uint32_t offA[4][2], offB[4][2];
    #pragma unroll
    for (int mf = 0; mf < 4; mf++)
        #pragma unroll
        for (int kk = 0; kk < 2; kk++) {
            int row = warp_m * 64 + mf * 16 + ra;
            int c   = kk * 2 + ha;
            offA[mf][kk] = row * 64 + ((c ^ ((row >> 1) & 3)) << 4);
        }
    #pragma unroll
    for (int nf4 = 0; nf4 < 4; nf4++)
        #pragma unroll
        for (int kk = 0; kk < 2; kk++) {
            int row = warp_n * 64 + nf4 * 16 + rb;
            int c   = kk * 2 + hb;
            offB[nf4][kk] = 8192 + row * 64 + ((c ^ ((row >> 1) & 3)) << 4);
        }

    auto fill = [&](int stage, int kg) {
        const uint32_t base = sbase + stage * K3_STG;
        const int kgo = kg * 32;
        #pragma unroll
        for (int s = 0; s < 4; s++) {
            int q = s * 128 + tid;
            int r = q >> 2, c = q & 3;
            uint32_t sw = r * 64 + ((c ^ ((r >> 1) & 3)) << 4);
            cp16(base + sw,        g_W2h + (size_t)(i0 + r) * HH + kgo + c * 8);
            cp16(base + 8192 + sw, g_BTh + (size_t)(j0 + r) * HH + kgo + c * 8);
        }
        cp_commit();
    };

    float acc[4][8][4];
    #pragma unroll
    for (int mf = 0; mf < 4; mf++)
        #pragma unroll
        for (int nf = 0; nf < 8; nf++)
            #pragma unroll
            for (int q = 0; q < 4; q++) acc[mf][nf][q] = 0.f;

    fill(0, 0);
    fill(1, 1);

    for (int kg = 0; kg < NKG3; ++kg) {
        cp_wait<1>();
        __syncthreads();
        if (kg + 2 < NKG3) fill((kg + 2) % 3, kg + 2);
        const uint32_t base = sbase + (kg % 3) * K3_STG;
        #pragma unroll
        for (int kk = 0; kk < 2; kk++) {
            uint32_t a[4][4], bh[8][2];
            #pragma unroll
            for (int mf = 0; mf < 4; mf++)
                LDSM4(a[mf][0], a[mf][1], a[mf][2], a[mf][3], base + offA[mf][kk]);
            #pragma unroll
            for (int nf4 = 0; nf4 < 4; nf4++) {
                uint32_t r0, r1, r2, r3;
                LDSM4(r0, r1, r2, r3, base + offB[nf4][kk]);
                bh[nf4 * 2][0] = r0;     bh[nf4 * 2][1] = r1;
                bh[nf4 * 2 + 1][0] = r2; bh[nf4 * 2 + 1][1] = r3;
            }
            #pragma unroll
            for (int mf = 0; mf < 4; mf++)
                #pragma unroll
                for (int nf = 0; nf < 8; nf++)
                    MMA16816F(acc[mf][nf], a[mf], bh[nf]);
        }
    }

    // epilogue: store E2 tile + fused per-row |.| partial sums
    const int er = lane >> 2;
    const int ec = (lane & 3) * 2;
    #pragma unroll
    for (int mf = 0; mf < 4; mf++) {
        float sa = 0.f, sb = 0.f;
        #pragma unroll
        for (int nf = 0; nf < 8; nf++) {
            int row = i0 + warp_m * 64 + mf * 16 + er;
            int col = j0 + warp_n * 64 + nf * 8 + ec;
            *(float2*)(g_E2s + (size_t)row * NE + col)       = make_float2(acc[mf][nf][0], acc[mf][nf][1]);
            *(float2*)(g_E2s + (size_t)(row + 8) * NE + col) = make_float2(acc[mf][nf][2], acc[mf][nf][3]);
            sa += fabsf(acc[mf][nf][0]) + fabsf(acc[mf][nf][1]);
            sb += fabsf(acc[mf][nf][2]) + fabsf(acc[mf][nf][3]);
        }
        // reduce across the 4 lanes sharing a row (lane&3)
        sa += __shfl_xor_sync(0xffffffffu, sa, 1);
        sa += __shfl_xor_sync(0xffffffffu, sa, 2);
        sb += __shfl_xor_sync(0xffffffffu, sb, 1);
        sb += __shfl_xor_sync(0xffffffffu, sb, 2);
        if ((lane & 3) == 0) {
            rs[warp_n][warp_m * 64 + mf * 16 + er]     = sa;
            rs[warp_n][warp_m * 64 + mf * 16 + 8 + er] = sb;
        }
    }
    __syncthreads();
    // combine the two warp_n halves; one thread per row
    {
        int row = tid;   // 0..127
        float v = rs[0][row] + rs[1][row];
        g_rpart[blockIdx.x][i0 + row] = v;
    }
}

// ---- K4: tiny — combine 8 jtile partials + ReLU params ----
__global__ void k4_relu2(const float* __restrict__ b2) {
    int row = blockIdx.x * 256 + threadIdx.x;
    float sr = 0.f;
    #pragma unroll
    for (int jt = 0; jt < NJT; jt++) sr += g_rpart[jt][row];
    sr += fabsf(g_tcol[row]);
    float v = g_vcol[row] + b2[row];
    float s, t, vn;
    relu_params(v, sr, s, t, vn);
    g_s2[row] = s; g_t2[row] = t; g_v2p[row] = vn;
}

// ---- K5: layer-3 partial GEMM (16-way deterministic k-split) ----
__global__ void k5_e3(const float* __restrict__ W3) {
    __shared__ float w3s[OO][256];
    __shared__ float s2s[256];
    const int jt = blockIdx.x, ks = blockIdx.y;
    const int k0 = ks * 256;
    const int tid = threadIdx.x;

    for (int idx = tid; idx < OO * 256; idx += 128) {
        int i = idx >> 8, kk = idx & 255;
        w3s[i][kk] = W3[(size_t)i * HH + k0 + kk];
    }
    for (int kk = tid; kk < 256; kk += 128) s2s[kk] = g_s2[k0 + kk];
    __syncthreads();

    const int j = jt * 128 + tid;
    float acc[OO];
    #pragma unroll
    for (int i = 0; i < OO; i++) acc[i] = 0.f;

    if (j < 1024) {
        const float* e = g_E2s + (size_t)k0 * NE + j;
        for (int kk = 0; kk < 256; ++kk) {
            float bval = s2s[kk] * e[(size_t)kk * NE];
            #pragma unroll
            for (int i = 0; i < OO; i++) acc[i] += w3s[i][kk] * bval;
        }
    } else if (j == 1024) {
        for (int kk = 0; kk < 256; ++kk) {
            float bval = s2s[kk] * g_tcol[k0 + kk];
            #pragma unroll
            for (int i = 0; i < OO; i++) acc[i] += w3s[i][kk] * bval;
        }
    } else if (j == 1025) {
        for (int kk = 0; kk < 256; ++kk) {
            float bval = g_t2[k0 + kk];
            #pragma unroll
            for (int i = 0; i < OO; i++) acc[i] += w3s[i][kk] * bval;
        }
    } else if (j == 1026) {
        for (int kk = 0; kk < 256; ++kk) {
            float bval = g_v2p[k0 + kk];
            #pragma unroll
            for (int i = 0; i < OO; i++) acc[i] += w3s[i][kk] * bval;
        }
    }
    if (j < NC3) {
        #pragma unroll
        for (int i = 0; i < OO; i++)
            g_E3p[((size_t)ks * OO + i) * SE3 + j] = acc[i];
    }
}

// ---- K6 ----
__global__ void k6_final(const float* __restrict__ b3, float* __restrict__ out) {
    const int i = blockIdx.x;
    const int tid = threadIdx.x;
    __shared__ float red[256];
    __shared__ float vsh;
    float racc = 0.f;
    for (int j = tid; j < NC3; j += 256) {
        float s = 0.f;
        #pragma unroll
        for (int ks = 0; ks < KS3; ks++) s += g_E3p[((size_t)ks * OO + i) * SE3 + j];
        if (j < 1026) racc += fabsf(s);
        else          vsh = s + b3[i];
    }
    red[tid] = racc;
    __syncthreads();
    for (int o = 128; o; o >>= 1) {
        if (tid < o) red[tid] += red[tid + o];
        __syncthreads();
    }
    if (tid == 0) {
        float v = vsh, r = red[0];
        out[i]      = v + r;
        out[10 + i] = v - r;
    }
}

extern "C" void kernel_launch(void* const* d_in, const int* in_sizes, int n_in,
                              void* d_out, int out_size) {
    const float* inputs = (const float*)d_in[0];
    const float* W1     = (const float*)d_in[1];
    const float* b1     = (const float*)d_in[2];
    const float* W2     = (const float*)d_in[3];
    const float* b2     = (const float*)d_in[4];
    const float* W3     = (const float*)d_in[5];
    const float* b3     = (const float*)d_in[6];
    float* out = (float*)d_out;

    static cudaStream_t sA = nullptr, sB = nullptr;
    static cudaEvent_t evF = nullptr, evA = nullptr, evK = nullptr, evB = nullptr;
    if (!sA) {
        cudaStreamCreateWithFlags(&sA, cudaStreamNonBlocking);
        cudaStreamCreateWithFlags(&sB, cudaStreamNonBlocking);
        cudaEventCreateWithFlags(&evF, cudaEventDisableTiming);
        cudaEventCreateWithFlags(&evA, cudaEventDisableTiming);
        cudaEventCreateWithFlags(&evK, cudaEventDisableTiming);
        cudaEventCreateWithFlags(&evB, cudaEventDisableTiming);
        cudaFuncSetAttribute(k3_mma, cudaFuncAttributeMaxDynamicSharedMemorySize, K3_SMEM);
    }

    // fork: W2 fp16 convert on side stream A
    cudaEventRecord(evF, 0);
    cudaStreamWaitEvent(sA, evF, 0);
    k2a_convW2<<<((size_t)HH * HH / 4) / 256, 256, 0, sA>>>(W2);
    cudaEventRecord(evA, sA);

    // main chain
    k0_init<<<1, DD>>>(inputs);
    k1_layer1<<<HH / 8, 256>>>(W1, b1);

    // fork: t/v matvec on side stream B (needs k1 only)
    cudaEventRecord(evK, 0);
    cudaStreamWaitEvent(sB, evK, 0);
    k3b_tv<<<HH / 8, 256, 0, sB>>>(W2);
    cudaEventRecord(evB, sB);

    dim3 g2b(HH / 32, DD / 32);
    k2b_buildBT<<<g2b, 256>>>(W1);

    cudaStreamWaitEvent(0, evA, 0);
    dim3 g3(NE / 128, HH / 128);          // 256 CTAs, one wave @ occ 2
    k3_mma<<<g3, 128, K3_SMEM>>>();

    cudaStreamWaitEvent(0, evB, 0);
    k4_relu2<<<HH / 256, 256>>>(b2);
    dim3 g5(9, KS3);
    k5_e3<<<g5, 128>>>(W3);
    k6_final<<<OO, 256>>>(b3, out);
}

// round 11
// speedup vs baseline: 6.3719x; 1.0582x over previous
#include <cuda_runtime.h>
#include <cuda_fp16.h>
#include <cstdint>

// Zonotope propagation: D=1024 -> H=4096 -> H=4096 -> O=10
// E2 = W2 @ Baug via single-pass fp16 mma.sync (fp32 acc), rel_err ~6e-6.
// R10: W2 fp32->fp16 conversion fused into k3's A-load path (k2a eliminated);
//      k0 merged into k1; tail cp_wait race fixed; k5 k-split 32.

#define DD 1024
#define HH 4096
#define OO 10
#define NE 1024
#define NC3 1027
#define SE3 1056
#define KS3 32
#define NJT 8

#define C_EPS   0.01f
#define C_MEAN  0.1307f
#define C_SIGMA 0.3081f

// ---- device scratch ----
__device__ float g_s1[HH];
__device__ float g_t1[HH];
__device__ float g_v1p[HH];
__device__ float g_d[DD];
__device__ __half g_BTh[(size_t)NE * HH];      // 8.4 MB (BaugT fp16, K-major)
__device__ float g_E2s[(size_t)HH * NE];       // 16.8 MB
__device__ float g_rpart[NJT][HH];
__device__ float g_tcol[HH];
__device__ float g_vcol[HH];
__device__ float g_s2[HH];
__device__ float g_t2[HH];
__device__ float g_v2p[HH];
__device__ float g_E3p[KS3 * OO * SE3];

// ================= PTX helpers =================
static __device__ __forceinline__ uint32_t smem_u32(const void* p) {
    uint32_t a;
    asm("{ .reg .u64 t; cvta.to.shared.u64 t, %1; cvt.u32.u64 %0, t; }" : "=r"(a) : "l"(p));
    return a;
}
static __device__ __forceinline__ void cp16(uint32_t dst, const void* src) {
    asm volatile("cp.async.cg.shared.global [%0], [%1], 16;" :: "r"(dst), "l"(src));
}
static __device__ __forceinline__ void cp_commit() {
    asm volatile("cp.async.commit_group;" ::: "memory");
}
template <int N> static __device__ __forceinline__ void cp_wait() {
    asm volatile("cp.async.wait_group %0;" :: "n"(N) : "memory");
}
#define LDSM4(r0, r1, r2, r3, addr) \
    asm volatile("ldmatrix.sync.aligned.m8n8.x4.shared.b16 {%0,%1,%2,%3}, [%4];" \
                 : "=r"(r0), "=r"(r1), "=r"(r2), "=r"(r3) : "r"(addr))
#define MMA16816F(c, a, b) \
    asm volatile("mma.sync.aligned.m16n8k16.row.col.f32.f16.f16.f32 " \
                 "{%0,%1,%2,%3}, {%4,%5,%6,%7}, {%8,%9}, {%0,%1,%2,%3};" \
                 : "+f"((c)[0]), "+f"((c)[1]), "+f"((c)[2]), "+f"((c)[3]) \
                 : "r"((a)[0]), "r"((a)[1]), "r"((a)[2]), "r"((a)[3]), \
                   "r"((b)[0]), "r"((b)[1]))
#define STS128(addr, u0, u1, u2, u3) \
    asm volatile("st.shared.v4.b32 [%0], {%1,%2,%3,%4};" \
                 :: "r"(addr), "r"(u0), "r"(u1), "r"(u2), "r"(u3) : "memory")

static __device__ __forceinline__ void relu_params(float v, float r,
                                                   float& s, float& t, float& vn) {
    float u = v + r;
    float l = v - r;
    if (u <= 0.f)       { s = 0.f; t = 0.f; vn = 0.f; }
    else if (l < 0.f)   { float slope = u / (u - l); float term = (1.f - slope) * u * 0.5f;
                          s = slope; t = term; vn = slope * v + term; }
    else                { s = 1.f; t = 0.f; vn = v; }
}
static __device__ __forceinline__ uint32_t h2u(__half2 h) {
    return *reinterpret_cast<uint32_t*>(&h);
}

// ---- K01: fused init + layer-1 (per-block v0/d in smem) ----
__global__ void k01_layer1(const float* __restrict__ in,
                           const float* __restrict__ W1, const float* __restrict__ b1) {
    __shared__ __align__(16) float sv0[DD];
    __shared__ __align__(16) float sd[DD];
    const int tid = threadIdx.x;
    for (int j = tid; j < DD; j += 256) {
        float x  = in[j];
        float up = fminf(x + C_EPS, 1.f);
        float lo = fmaxf(x - C_EPS, 0.f);
        float val = up + lo;
        sv0[j] = (val - C_MEAN) / C_SIGMA;
        sd[j]  = up / C_SIGMA;
    }
    __syncthreads();
    if (blockIdx.x == 0) {   // one block also publishes d for k2b
        for (int j = tid; j < DD; j += 256) g_d[j] = sd[j];
    }
    int row  = blockIdx.x * 8 + (tid >> 5);
    int lane = tid & 31;
    const float* w = W1 + (size_t)row * DD;
    float sv = 0.f, sr = 0.f;
    #pragma unroll
    for (int j = lane * 4; j < DD; j += 128) {
        float4 wv = *(const float4*)(w + j);
        float4 v  = *(const float4*)(sv0 + j);
        float4 dd = *(const float4*)(sd + j);
        sv += wv.x * v.x + wv.y * v.y + wv.z * v.z + wv.w * v.w;
        sr += fabsf(wv.x) * dd.x + fabsf(wv.y) * dd.y
            + fabsf(wv.z) * dd.z + fabsf(wv.w) * dd.w;
    }
    #pragma unroll
    for (int o = 16; o; o >>= 1) {
        sv += __shfl_xor_sync(0xffffffffu, sv, o);
        sr += __shfl_xor_sync(0xffffffffu, sr, o);
    }
    if (lane == 0) {
        float v = sv + b1[row];
        float s, t, vn;
        relu_params(v, sr, s, t, vn);
        g_s1[row] = s; g_t1[row] = t; g_v1p[row] = vn;
    }
}

// ---- K2b: BaugT rows 0..1023 in fp16 ----
__global__ void k2b_buildBT(const float* __restrict__ W1) {
    __shared__ float ts[32][33];
    int k0 = blockIdx.x * 32;
    int j0 = blockIdx.y * 32;
    int tx = threadIdx.x & 31, ty = threadIdx.x >> 5;
    #pragma unroll
    for (int r = 0; r < 4; r++) {
        int k = k0 + ty + r * 8;
        ts[ty + r * 8][tx] = W1[(size_t)k * DD + j0 + tx] * g_s1[k];
    }
    __syncthreads();
    #pragma unroll
    for (int r = 0; r < 4; r++) {
        int j = j0 + ty + r * 8;
        float x = ts[tx][ty + r * 8] * g_d[j];
        g_BTh[(size_t)j * HH + k0 + tx] = __float2half_rn(x);
    }
}

// ---- K3b: t/v columns of E2 via fp32 matvec (side stream) ----
__global__ void k3b_tv(const float* __restrict__ W2) {
    int row  = blockIdx.x * 8 + (threadIdx.x >> 5);
    int lane = threadIdx.x & 31;
    const float* w = W2 + (size_t)row * HH;
    float st = 0.f, sv = 0.f;
    for (int j = lane * 4; j < HH; j += 128) {
        float4 wv = *(const float4*)(w + j);
        float4 tt = *(const float4*)(g_t1 + j);
        float4 vv = *(const float4*)(g_v1p + j);
        st += wv.x * tt.x + wv.y * tt.y + wv.z * tt.z + wv.w * tt.w;
        sv += wv.x * vv.x + wv.y * vv.y + wv.z * vv.z + wv.w * vv.w;
    }
    #pragma unroll
    for (int o = 16; o; o >>= 1) {
        st += __shfl_xor_sync(0xffffffffu, st, o);
        sv += __shfl_xor_sync(0xffffffffu, sv, o);
    }
    if (lane == 0) { g_tcol[row] = st; g_vcol[row] = sv; }
}

// ================== K3: fp16 GEMM w/ fused A-conversion (fp32 W2 direct) =====
// Stage 16KB: A-fp16 @0 (STS-converted), B-fp16 @8K (cp.async). 3-stage ring.
// Grid (8, 32), 128 thr, occ 2. Fused row-|.| epilogue.
#define K3_STG 16384
#define K3_SMEM (3 * K3_STG)
#define NKG3 128

__global__ __launch_bounds__(128, 2) void k3_mma(const float* __restrict__ W2) {
    extern __shared__ __align__(1024) unsigned char sm[];
    __shared__ float rs[2][128];
    const int tid  = threadIdx.x;
    const int lane = tid & 31;
    const int wid  = tid >> 5;
    const int warp_m = wid & 1;
    const int warp_n = wid >> 1;
    const int j0 = blockIdx.x * 128;
    const int i0 = blockIdx.y * 128;
    const uint32_t sbase = smem_u32(sm);

    const int ra = (lane & 7) + (((lane >> 3) & 1) << 3);
    const int ha = lane >> 4;
    const int rb = (lane & 7) + ((lane >> 4) << 3);
    const int hb = (lane >> 3) & 1;
    uint32_t offA[4][2], offB[4][2];
    #pragma unroll
    for (int mf = 0; mf < 4; mf++)
        #pragma unroll
        for (int kk = 0; kk < 2; kk++) {
            int row = warp_m * 64 + mf * 16 + ra;
            int c   = kk * 2 + ha;
            offA[mf][kk] = row * 64 + ((c ^ ((row >> 1) & 3)) << 4);
        }
    #pragma unroll
    for (int nf4 = 0; nf4 < 4; nf4++)
        #pragma unroll
        for (int kk = 0; kk < 2; kk++) {
            int row = warp_n * 64 + nf4 * 16 + rb;
            int c   = kk * 2 + hb;
            offB[nf4][kk] = 8192 + row * 64 + ((c ^ ((row >> 1) & 3)) << 4);
        }

    // thread's A chunk coords (4 chunks of 8 k-values)
    int crow[4], ccol[4];
    uint32_t csw[4];
    #pragma unroll
    for (int s = 0; s < 4; s++) {
        int q = s * 128 + tid;
        crow[s] = q >> 2; ccol[s] = q & 3;
        csw[s] = crow[s] * 64 + ((ccol[s] ^ ((crow[s] >> 1) & 3)) << 4);
    }

    float4 aA[4][2];   // register-staged fp32 A (one k-group)
    auto ldgA = [&](int kg) {
        const int kgo = kg * 32;
        #pragma unroll
        for (int s = 0; s < 4; s++) {
            const float* gp = W2 + (size_t)(i0 + crow[s]) * HH + kgo + ccol[s] * 8;
            aA[s][0] = *(const float4*)gp;
            aA[s][1] = *(const float4*)(gp + 4);
        }
    };
    auto stsA = [&](int stage) {
        const uint32_t base = sbase + stage * K3_STG;
        #pragma unroll
        for (int s = 0; s < 4; s++) {
            __half2 h0 = __floats2half2_rn(aA[s][0].x, aA[s][0].y);
            __half2 h1 = __floats2half2_rn(aA[s][0].z, aA[s][0].w);
            __half2 h2 = __floats2half2_rn(aA[s][1].x, aA[s][1].y);
            __half2 h3 = __floats2half2_rn(aA[s][1].z, aA[s][1].w);
            STS128(base + csw[s], h2u(h0), h2u(h1), h2u(h2), h2u(h3));
        }
    };
    auto cpB = [&](int stage, int kg) {
        const uint32_t base = sbase + stage * K3_STG + 8192;
        const int kgo = kg * 32;
        #pragma unroll
        for (int s = 0; s < 4; s++)
            cp16(base + csw[s], g_BTh + (size_t)(j0 + crow[s]) * HH + kgo + ccol[s] * 8);
        cp_commit();
    };

    float acc[4][8][4];
    #pragma unroll
    for (int mf = 0; mf < 4; mf++)
        #pragma unroll
        for (int nf = 0; nf < 8; nf++)
            #pragma unroll
            for (int q = 0; q < 4; q++) acc[mf][nf][q] = 0.f;

    ldgA(0);
    cpB(0, 0);
    cpB(1, 1);

    for (int kg = 0; kg < NKG3; ++kg) {
        stsA(kg % 3);                       // A(kg) regs -> smem
        if (kg + 1 < NKG3) ldgA(kg + 1);    // prefetch next A (WAR after STS)
        if (kg >= NKG3 - 2) cp_wait<0>();   // tail: drain fully (no race)
        else                cp_wait<1>();   // B(kg) ready, B(kg+1) in flight
        __syncthreads();                    // STS visible + B joined
        if (kg + 2 < NKG3) cpB((kg + 2) % 3, kg + 2);
        const uint32_t base = sbase + (kg % 3) * K3_STG;
        #pragma unroll
        for (int kk = 0; kk < 2; kk++) {
            uint32_t a[4][4], bh[8][2];
            #pragma unroll
            for (int mf = 0; mf < 4; mf++)
                LDSM4(a[mf][0], a[mf][1], a[mf][2], a[mf][3], base + offA[mf][kk]);
            #pragma unroll
            for (int nf4 = 0; nf4 < 4; nf4++) {
                uint32_t r0, r1, r2, r3;
                LDSM4(r0, r1, r2, r3, base + offB[nf4][kk]);
                bh[nf4 * 2][0] = r0;     bh[nf4 * 2][1] = r1;
                bh[nf4 * 2 + 1][0] = r2; bh[nf4 * 2 + 1][1] = r3;
            }
            #pragma unroll
            for (int mf = 0; mf < 4; mf++)
                #pragma unroll
                for (int nf = 0; nf < 8; nf++)
                    MMA16816F(acc[mf][nf], a[mf], bh[nf]);
        }
        __syncthreads();                    // protect stage reuse vs next STS
    }

    // epilogue: store E2 tile + fused per-row |.| partial sums
    const int er = lane >> 2;
    const int ec = (lane & 3) * 2;
    #pragma unroll
    for (int mf = 0; mf < 4; mf++) {
        float sa = 0.f, sb = 0.f;
        #pragma unroll
        for (int nf = 0; nf < 8; nf++) {
            int row = i0 + warp_m * 64 + mf * 16 + er;
            int col = j0 + warp_n * 64 + nf * 8 + ec;
            *(float2*)(g_E2s + (size_t)row * NE + col)       = make_float2(acc[mf][nf][0], acc[mf][nf][1]);
            *(float2*)(g_E2s + (size_t)(row + 8) * NE + col) = make_float2(acc[mf][nf][2], acc[mf][nf][3]);
            sa += fabsf(acc[mf][nf][0]) + fabsf(acc[mf][nf][1]);
            sb += fabsf(acc[mf][nf][2]) + fabsf(acc[mf][nf][3]);
        }
        sa += __shfl_xor_sync(0xffffffffu, sa, 1);
        sa += __shfl_xor_sync(0xffffffffu, sa, 2);
        sb += __shfl_xor_sync(0xffffffffu, sb, 1);
        sb += __shfl_xor_sync(0xffffffffu, sb, 2);
        if ((lane & 3) == 0) {
            rs[warp_n][warp_m * 64 + mf * 16 + er]     = sa;
            rs[warp_n][warp_m * 64 + mf * 16 + 8 + er] = sb;
        }
    }
    __syncthreads();
    {
        int row = tid;
        float v = rs[0][row] + rs[1][row];
        g_rpart[blockIdx.x][i0 + row] = v;
    }
}

// ---- K4: combine jtile partials + ReLU params ----
__global__ void k4_relu2(const float* __restrict__ b2) {
    int row = blockIdx.x * 256 + threadIdx.x;
    float sr = 0.f;
    #pragma unroll
    for (int jt = 0; jt < NJT; jt++) sr += g_rpart[jt][row];
    sr += fabsf(g_tcol[row]);
    float v = g_vcol[row] + b2[row];
    float s, t, vn;
    relu_params(v, sr, s, t, vn);
    g_s2[row] = s; g_t2[row] = t; g_v2p[row] = vn;
}

// ---- K5: layer-3 partial GEMM (32-way deterministic k-split) ----
__global__ void k5_e3(const float* __restrict__ W3) {
    __shared__ float w3s[OO][128];
    __shared__ float s2s[128];
    const int jt = blockIdx.x, ks = blockIdx.y;
    const int k0 = ks * 128;
    const int tid = threadIdx.x;

    for (int idx = tid; idx < OO * 128; idx += 128) {
        int i = idx >> 7, kk = idx & 127;
        w3s[i][kk] = W3[(size_t)i * HH + k0 + kk];
    }
    s2s[tid] = g_s2[k0 + tid];
    __syncthreads();

    const int j = jt * 128 + tid;
    float acc[OO];
    #pragma unroll
    for (int i = 0; i < OO; i++) acc[i] = 0.f;

    if (j < 1024) {
        const float* e = g_E2s + (size_t)k0 * NE + j;
        for (int kk = 0; kk < 128; ++kk) {
            float bval = s2s[kk] * e[(size_t)kk * NE];
            #pragma unroll
            for (int i = 0; i < OO; i++) acc[i] += w3s[i][kk] * bval;
        }
    } else if (j == 1024) {
        for (int kk = 0; kk < 128; ++kk) {
            float bval = s2s[kk] * g_tcol[k0 + kk];
            #pragma unroll
            for (int i = 0; i < OO; i++) acc[i] += w3s[i][kk] * bval;
        }
    } else if (j == 1025) {
        for (int kk = 0; kk < 128; ++kk) {
            float bval = g_t2[k0 + kk];
            #pragma unroll
            for (int i = 0; i < OO; i++) acc[i] += w3s[i][kk] * bval;
        }
    } else if (j == 1026) {
        for (int kk = 0; kk < 128; ++kk) {
            float bval = g_v2p[k0 + kk];
            #pragma unroll
            for (int i = 0; i < OO; i++) acc[i] += w3s[i][kk] * bval;
        }
    }
    if (j < NC3) {
        #pragma unroll
        for (int i = 0; i < OO; i++)
            g_E3p[((size_t)ks * OO + i) * SE3 + j] = acc[i];
    }
}

// ---- K6 ----
__global__ void k6_final(const float* __restrict__ b3, float* __restrict__ out) {
    const int i = blockIdx.x;
    const int tid = threadIdx.x;
    __shared__ float red[256];
    __shared__ float vsh;
    float racc = 0.f;
    for (int j = tid; j < NC3; j += 256) {
        float s = 0.f;
        #pragma unroll
        for (int ks = 0; ks < KS3; ks++) s += g_E3p[((size_t)ks * OO + i) * SE3 + j];
        if (j < 1026) racc += fabsf(s);
        else          vsh = s + b3[i];
    }
    red[tid] = racc;
    __syncthreads();
    for (int o = 128; o; o >>= 1) {
        if (tid < o) red[tid] += red[tid + o];
        __syncthreads();
    }
    if (tid == 0) {
        float v = vsh, r = red[0];
        out[i]      = v + r;
        out[10 + i] = v - r;
    }
}

extern "C" void kernel_launch(void* const* d_in, const int* in_sizes, int n_in,
                              void* d_out, int out_size) {
    const float* inputs = (const float*)d_in[0];
    const float* W1     = (const float*)d_in[1];
    const float* b1     = (const float*)d_in[2];
    const float* W2     = (const float*)d_in[3];
    const float* b2     = (const float*)d_in[4];
    const float* W3     = (const float*)d_in[5];
    const float* b3     = (const float*)d_in[6];
    float* out = (float*)d_out;

    static cudaStream_t sB = nullptr;
    static cudaEvent_t evK = nullptr, evB = nullptr;
    if (!sB) {
        cudaStreamCreateWithFlags(&sB, cudaStreamNonBlocking);
        cudaEventCreateWithFlags(&evK, cudaEventDisableTiming);
        cudaEventCreateWithFlags(&evB, cudaEventDisableTiming);
        cudaFuncSetAttribute(k3_mma, cudaFuncAttributeMaxDynamicSharedMemorySize, K3_SMEM);
    }

    // main chain
    k01_layer1<<<HH / 8, 256>>>(inputs, W1, b1);

    // fork: t/v matvec on side stream (needs k01 only)
    cudaEventRecord(evK, 0);
    cudaStreamWaitEvent(sB, evK, 0);
    k3b_tv<<<HH / 8, 256, 0, sB>>>(W2);
    cudaEventRecord(evB, sB);

    dim3 g2b(HH / 32, DD / 32);
    k2b_buildBT<<<g2b, 256>>>(W1);

    dim3 g3(NE / 128, HH / 128);          // 256 CTAs, one wave @ occ 2
    k3_mma<<<g3, 128, K3_SMEM>>>(W2);

    cudaStreamWaitEvent(0, evB, 0);
    k4_relu2<<<HH / 256, 256>>>(b2);
    dim3 g5(9, KS3);
    k5_e3<<<g5, 128>>>(W3);
    k6_final<<<OO, 256>>>(b3, out);
}